// round 5
// baseline (speedup 1.0000x reference)
#include <cuda_runtime.h>
#include <cuda_bf16.h>
#include <math.h>
#include <stdint.h>

#define NNODE 50000
#define NEDGE 500000
#define DMAX  256
#define EPS_SM 1e-16f
#define EPS_LN 1e-5f
#define NEG_SLOPE 0.2f

// ---------------- scratch (device globals) ----------------
__device__ float g_h[NNODE * DMAX];
__device__ float g_agg[NNODE * DMAX];
__device__ float g_alpha[NEDGE * 4];
__device__ float g_denom[NNODE * 4];
__device__ float g_ssrc[NNODE * 4];
__device__ float g_sdst[NNODE * 4];
__device__ int   g_cnt[NNODE];
__device__ int   g_rptr[NNODE + 1];
__device__ int   g_fill[NNODE];
__device__ int   g_redges[NEDGE];
__device__ __nv_bfloat16 g_ahi[NNODE * 384];
__device__ __nv_bfloat16 g_alo[NNODE * 384];
__device__ __nv_bfloat16 g_wthi[256 * 384];
__device__ __nv_bfloat16 g_wtlo[256 * 384];

// ================= PTX helpers =================
__device__ __forceinline__ uint32_t smem_u32(const void* p) {
    uint32_t a;
    asm("{ .reg .u64 t; cvta.to.shared.u64 t, %1; cvt.u32.u64 %0, t; }" : "=r"(a) : "l"(p));
    return a;
}

#define CPA16(dst, src, sz) \
    asm volatile("cp.async.cg.shared.global [%0], [%1], 16, %2;" \
                 :: "r"(dst), "l"(src), "r"(sz))
#define CPA_COMMIT() asm volatile("cp.async.commit_group;" ::: "memory")
#define CPA_WAIT(n)  asm volatile("cp.async.wait_group %0;" :: "n"(n) : "memory")

#define LDMX4(r0, r1, r2, r3, addr) \
    asm volatile("ldmatrix.sync.aligned.m8n8.x4.shared.b16 {%0,%1,%2,%3}, [%4];" \
                 : "=r"(r0), "=r"(r1), "=r"(r2), "=r"(r3) : "r"(addr))

__device__ __forceinline__ void mma16816(float* c, const uint32_t* a, const uint32_t* b) {
    asm volatile(
        "mma.sync.aligned.m16n8k16.row.col.f32.bf16.bf16.f32 "
        "{%0,%1,%2,%3}, {%4,%5,%6,%7}, {%8,%9}, {%0,%1,%2,%3};"
        : "+f"(c[0]), "+f"(c[1]), "+f"(c[2]), "+f"(c[3])
        : "r"(a[0]), "r"(a[1]), "r"(a[2]), "r"(a[3]), "r"(b[0]), "r"(b[1]));
}

#define SWZ64(b) ((b) ^ (((b) >> 3) & 0x30))

// ---------------- utility ----------------
__global__ void zero_i(int* p, int n) {
    int i = blockIdx.x * blockDim.x + threadIdx.x;
    if (i < n) p[i] = 0;
}
__global__ void zero_f(float* p, int n) {
    int i = blockIdx.x * blockDim.x + threadIdx.x;
    if (i < n) p[i] = 0.0f;
}

// ---------------- weight prep: transpose + bf16 split ----------------
__global__ void wprep_kernel(const float* __restrict__ W, __nv_bfloat16* hi,
                             __nv_bfloat16* lo, int K, int Nn) {
    int i = blockIdx.x * blockDim.x + threadIdx.x;
    if (i >= K * Nn) return;
    int n = i / K, k = i - n * K;
    float v = W[(size_t)k * Nn + n];
    __nv_bfloat16 h = __float2bfloat16(v);
    hi[i] = h;
    lo[i] = __float2bfloat16(v - __bfloat162float(h));
}

// ---------------- activation split (layer-1 input x) ----------------
__global__ void asplit_kernel(const float* __restrict__ A, __nv_bfloat16* hi,
                              __nv_bfloat16* lo, int total) {
    int i = blockIdx.x * blockDim.x + threadIdx.x;
    if (i >= total) return;
    float v = A[i];
    __nv_bfloat16 h = __float2bfloat16(v);
    hi[i] = h;
    lo[i] = __float2bfloat16(v - __bfloat162float(h));
}

// ---------------- CSR build ----------------
__global__ void hist_kernel(const int* __restrict__ row, int* cnt, int e) {
    int i = blockIdx.x * blockDim.x + threadIdx.x;
    if (i < e) atomicAdd(&cnt[row[i]], 1);
}

__global__ void scan_kernel(const int* __restrict__ cnt, int* ptr, int* fill, int n) {
    __shared__ int sh[1024];
    __shared__ int carry;
    if (threadIdx.x == 0) carry = 0;
    __syncthreads();
    for (int base = 0; base < n; base += 1024) {
        int i = base + threadIdx.x;
        int v = (i < n) ? cnt[i] : 0;
        sh[threadIdx.x] = v;
        __syncthreads();
        for (int off = 1; off < 1024; off <<= 1) {
            int t = (threadIdx.x >= off) ? sh[threadIdx.x - off] : 0;
            __syncthreads();
            sh[threadIdx.x] += t;
            __syncthreads();
        }
        int excl = sh[threadIdx.x] - v;
        if (i < n) { ptr[i] = carry + excl; fill[i] = carry + excl; }
        __syncthreads();
        if (threadIdx.x == 1023) carry += sh[1023];
        __syncthreads();
    }
    if (threadIdx.x == 0) ptr[n] = carry;
}

__global__ void scatter_kernel(const int* __restrict__ row, int* fill, int* redges, int e) {
    int i = blockIdx.x * blockDim.x + threadIdx.x;
    if (i < e) {
        int pos = atomicAdd(&fill[row[i]], 1);
        redges[pos] = i;
    }
}

// ============ HMMA split-bf16 GEMM, 4-stage cp.async pipeline ============
// CTA tile 128(m) x 64(n), BK=32, 8 warps (4m x 2n), warp tile 32x32.
template <int NN, int KK>
__global__ __launch_bounds__(256, 2) void gemm_mma(
    const __nv_bfloat16* __restrict__ Ahi, const __nv_bfloat16* __restrict__ Alo,
    const __nv_bfloat16* __restrict__ Bhi, const __nv_bfloat16* __restrict__ Blo,
    float* __restrict__ C, int M)
{
    constexpr int BK = 32;
    constexpr int NCH = KK / BK;
    constexpr int STG = 24576;   // A hi 8K | A lo 8K | B hi 4K | B lo 4K
    extern __shared__ char smem[];
    uint32_t sb = smem_u32(smem);

    int tid = threadIdx.x;
    int lane = tid & 31, wid = tid >> 5;
    int wm = wid & 3, wn = wid >> 2;
    int m0 = blockIdx.y * 128;
    int n0 = blockIdx.x * 64;

    // ldmatrix addresses (stage-relative)
    int g = lane >> 3, lr = lane & 7;
    uint32_t aoff[2][2], boff[2][2];
#pragma unroll
    for (int mt = 0; mt < 2; mt++)
#pragma unroll
        for (int ks = 0; ks < 2; ks++) {
            int row = wm * 32 + mt * 16 + (g & 1) * 8 + lr;
            int unit = ks * 2 + (g >> 1);
            aoff[mt][ks] = SWZ64(row * 64 + unit * 16);
        }
#pragma unroll
    for (int np = 0; np < 2; np++)
#pragma unroll
        for (int ks = 0; ks < 2; ks++) {
            int row = wn * 32 + np * 16 + (g >> 1) * 8 + lr;
            int unit = ks * 2 + (g & 1);
            boff[np][ks] = 16384u + SWZ64(row * 64 + unit * 16);
        }

    // cp.async slots
    int ar0 = tid >> 2, au0 = tid & 3;
    int ar1 = (tid + 256) >> 2;
    uint32_t asw0 = SWZ64(ar0 * 64 + au0 * 16);
    uint32_t asw1 = SWZ64(ar1 * 64 + au0 * 16);
    int br = tid >> 2, bu = tid & 3;
    uint32_t bsw = SWZ64(br * 64 + bu * 16);
    long bofs = (long)(n0 + br) * KK + bu * 8;

    float acc[2][4][4];
#pragma unroll
    for (int mt = 0; mt < 2; mt++)
#pragma unroll
        for (int nt = 0; nt < 4; nt++)
#pragma unroll
            for (int j = 0; j < 4; j++) acc[mt][nt][j] = 0.f;

    auto load_stage = [&](int ch, uint32_t so) {
        int k0 = ch * BK;
        {
            int grow = m0 + ar0;
            int sz = (grow < M) ? 16 : 0;
            long go = (long)((grow < M) ? grow : 0) * KK + k0 + au0 * 8;
            CPA16(sb + so + asw0, Ahi + go, sz);
            CPA16(sb + so + 8192 + asw0, Alo + go, sz);
        }
        {
            int grow = m0 + ar1;
            int sz = (grow < M) ? 16 : 0;
            long go = (long)((grow < M) ? grow : 0) * KK + k0 + au0 * 8;
            CPA16(sb + so + asw1, Ahi + go, sz);
            CPA16(sb + so + 8192 + asw1, Alo + go, sz);
        }
        {
            long go = bofs + k0;
            CPA16(sb + so + 16384 + bsw, Bhi + go, 16);
            CPA16(sb + so + 20480 + bsw, Blo + go, 16);
        }
    };

    auto compute_stage = [&](uint32_t so) {
#pragma unroll
        for (int ks = 0; ks < 2; ks++) {
            uint32_t ah[2][4], al[2][4], bh[4][2], bl[4][2];
#pragma unroll
            for (int mt = 0; mt < 2; mt++) {
                LDMX4(ah[mt][0], ah[mt][1], ah[mt][2], ah[mt][3], sb + so + aoff[mt][ks]);
                LDMX4(al[mt][0], al[mt][1], al[mt][2], al[mt][3], sb + so + 8192 + aoff[mt][ks]);
            }
#pragma unroll
            for (int np = 0; np < 2; np++) {
                LDMX4(bh[2 * np][0], bh[2 * np][1], bh[2 * np + 1][0], bh[2 * np + 1][1],
                      sb + so + boff[np][ks]);
                LDMX4(bl[2 * np][0], bl[2 * np][1], bl[2 * np + 1][0], bl[2 * np + 1][1],
                      sb + so + 4096 + boff[np][ks]);
            }
#pragma unroll
            for (int mt = 0; mt < 2; mt++)
#pragma unroll
                for (int nt = 0; nt < 4; nt++) {
                    mma16816(acc[mt][nt], ah[mt], bh[nt]);
                    mma16816(acc[mt][nt], ah[mt], bl[nt]);
                    mma16816(acc[mt][nt], al[mt], bh[nt]);
                }
        }
    };

    // 4-stage pipeline, one __syncthreads per chunk
    load_stage(0, 0);
    CPA_COMMIT();
    load_stage(1, STG);
    CPA_COMMIT();
    load_stage(2, 2 * STG);
    CPA_COMMIT();
#pragma unroll 1
    for (int ch = 0; ch < NCH; ch++) {
        uint32_t so = (uint32_t)(ch & 3) * STG;
        if (ch + 2 < NCH) { CPA_WAIT(2); }
        else if (ch + 1 < NCH) { CPA_WAIT(1); }
        else { CPA_WAIT(0); }
        __syncthreads();
        if (ch + 3 < NCH) {
            load_stage(ch + 3, (uint32_t)((ch + 3) & 3) * STG);
            CPA_COMMIT();
        }
        compute_stage(so);
    }

    // epilogue
#pragma unroll
    for (int mt = 0; mt < 2; mt++) {
        int m = m0 + wm * 32 + mt * 16 + (lane >> 2);
#pragma unroll
        for (int nt = 0; nt < 4; nt++) {
            int n = n0 + wn * 32 + nt * 8 + (lane & 3) * 2;
            if (m < M)
                *reinterpret_cast<float2*>(C + (size_t)m * NN + n) =
                    make_float2(acc[mt][nt][0], acc[mt][nt][1]);
            if (m + 8 < M)
                *reinterpret_cast<float2*>(C + (size_t)(m + 8) * NN + n) =
                    make_float2(acc[mt][nt][2], acc[mt][nt][3]);
        }
    }
}

// ---------------- per-node attention scores ----------------
__global__ void attn_scores_kernel(
    const float* __restrict__ h, const float* __restrict__ asrc, const float* __restrict__ adst,
    float* __restrict__ ssrc, float* __restrict__ sdst, int n, int H, int C)
{
    int wid = (blockIdx.x * blockDim.x + threadIdx.x) >> 5;
    int lane = threadIdx.x & 31;
    if (wid >= n * H) return;
    int node = wid / H, hh = wid - node * H;
    const float* hp = h + (size_t)node * H * C + hh * C;
    const float* ap = asrc + hh * C;
    const float* dp = adst + hh * C;
    float ss = 0.f, sd = 0.f;
    for (int c = lane; c < C; c += 32) {
        float v = hp[c];
        ss += v * ap[c];
        sd += v * dp[c];
    }
#pragma unroll
    for (int o = 16; o; o >>= 1) {
        ss += __shfl_xor_sync(0xffffffffu, ss, o);
        sd += __shfl_xor_sync(0xffffffffu, sd, o);
    }
    if (lane == 0) { ssrc[wid] = ss; sdst[wid] = sd; }
}

// ---------------- edge scores H=4 (vectorized) ----------------
__global__ void edge_scores4_kernel(
    const int* __restrict__ row, const int* __restrict__ col, const float* __restrict__ ew,
    const float* __restrict__ ssrc, const float* __restrict__ sdst,
    float* __restrict__ aexp, float* __restrict__ denom, int e)
{
    int i = blockIdx.x * blockDim.x + threadIdx.x;
    if (i >= e) return;
    int r = row[i], c = col[i];
    float w = ew[i];
    float4 s4 = *reinterpret_cast<const float4*>(ssrc + (size_t)r * 4);
    float4 d4 = *reinterpret_cast<const float4*>(sdst + (size_t)c * 4);
    float4 o;
    float v;
    v = s4.x + d4.x; v = (v >= 0.f) ? v : NEG_SLOPE * v; o.x = expf(v * w);
    v = s4.y + d4.y; v = (v >= 0.f) ? v : NEG_SLOPE * v; o.y = expf(v * w);
    v = s4.z + d4.z; v = (v >= 0.f) ? v : NEG_SLOPE * v; o.z = expf(v * w);
    v = s4.w + d4.w; v = (v >= 0.f) ? v : NEG_SLOPE * v; o.w = expf(v * w);
    *reinterpret_cast<float4*>(aexp + (size_t)i * 4) = o;
    atomicAdd(&denom[c * 4 + 0], o.x);
    atomicAdd(&denom[c * 4 + 1], o.y);
    atomicAdd(&denom[c * 4 + 2], o.z);
    atomicAdd(&denom[c * 4 + 3], o.w);
}

// ---------------- edge scores H=1 ----------------
__global__ void edge_scores1_kernel(
    const int* __restrict__ row, const int* __restrict__ col, const float* __restrict__ ew,
    const float* __restrict__ ssrc, const float* __restrict__ sdst,
    float* __restrict__ aexp, float* __restrict__ denom, int e)
{
    int i = blockIdx.x * blockDim.x + threadIdx.x;
    if (i >= e) return;
    int r = row[i], c = col[i];
    float v = ssrc[r] + sdst[c];
    v = (v >= 0.f) ? v : NEG_SLOPE * v;
    v = expf(v * ew[i]);
    aexp[i] = v;
    atomicAdd(&denom[c], v);
}

// ---------------- reciprocal of denominators ----------------
__global__ void rdenom_kernel(float* d, int n) {
    int i = blockIdx.x * blockDim.x + threadIdx.x;
    if (i < n) d[i] = 1.0f / (d[i] + EPS_SM);
}

// -------- aggregation D=256 H=4: TWO warps per node, 128 cols each --------
__global__ __launch_bounds__(256) void aggregate256_kernel(
    const float* __restrict__ h, const float* __restrict__ aexp, const float* __restrict__ rden,
    const int* __restrict__ col, const int* __restrict__ rptr, const int* __restrict__ redges,
    const float* __restrict__ bias, float* __restrict__ out, int n)
{
    int gw = (blockIdx.x * blockDim.x + threadIdx.x) >> 5;
    int lane = threadIdx.x & 31;
    if (gw >= n * 2) return;
    int node = gw >> 1, half = gw & 1;
    int cb = half * 128 + lane * 4;     // this lane's 4 contiguous columns
    int hh = cb >> 6;                   // head index (lane-group uniform)
    float4 a0 = make_float4(0.f, 0.f, 0.f, 0.f);
    int s = rptr[node], e1 = rptr[node + 1];
    int i = s;
    for (; i + 1 < e1; i += 2) {
        int ea = redges[i], eb = redges[i + 1];
        int ca = col[ea], cb2 = col[eb];
        float wa = aexp[(size_t)ea * 4 + hh] * rden[(size_t)ca * 4 + hh];
        float wb = aexp[(size_t)eb * 4 + hh] * rden[(size_t)cb2 * 4 + hh];
        float4 va = *reinterpret_cast<const float4*>(h + (size_t)ca * 256 + cb);
        float4 vb = *reinterpret_cast<const float4*>(h + (size_t)cb2 * 256 + cb);
        a0.x += wa * va.x; a0.y += wa * va.y; a0.z += wa * va.z; a0.w += wa * va.w;
        a0.x += wb * vb.x; a0.y += wb * vb.y; a0.z += wb * vb.z; a0.w += wb * vb.w;
    }
    if (i < e1) {
        int e = redges[i];
        int c = col[e];
        float w = aexp[(size_t)e * 4 + hh] * rden[(size_t)c * 4 + hh];
        float4 v = *reinterpret_cast<const float4*>(h + (size_t)c * 256 + cb);
        a0.x += w * v.x; a0.y += w * v.y; a0.z += w * v.z; a0.w += w * v.w;
    }
    float4 b0 = *reinterpret_cast<const float4*>(bias + cb);
    a0.x += b0.x; a0.y += b0.y; a0.z += b0.z; a0.w += b0.w;
    *reinterpret_cast<float4*>(out + (size_t)node * 256 + cb) = a0;
}

// -------- aggregation D=128 H=1: warp per node --------
__global__ __launch_bounds__(256) void aggregate128_kernel(
    const float* __restrict__ h, const float* __restrict__ aexp, const float* __restrict__ rden,
    const int* __restrict__ col, const int* __restrict__ rptr, const int* __restrict__ redges,
    const float* __restrict__ bias, float* __restrict__ out, int n)
{
    int warp = (blockIdx.x * blockDim.x + threadIdx.x) >> 5;
    int lane = threadIdx.x & 31;
    if (warp >= n) return;
    float4 a0 = make_float4(0.f, 0.f, 0.f, 0.f);
    int s = rptr[warp], e1 = rptr[warp + 1];
    int i = s;
    for (; i + 1 < e1; i += 2) {
        int ea = redges[i], eb = redges[i + 1];
        int ca = col[ea], cb = col[eb];
        float wa = aexp[ea] * rden[ca];
        float wb = aexp[eb] * rden[cb];
        float4 va = *reinterpret_cast<const float4*>(h + (size_t)ca * 128 + lane * 4);
        float4 vb = *reinterpret_cast<const float4*>(h + (size_t)cb * 128 + lane * 4);
        a0.x += wa * va.x; a0.y += wa * va.y; a0.z += wa * va.z; a0.w += wa * va.w;
        a0.x += wb * vb.x; a0.y += wb * vb.y; a0.z += wb * vb.z; a0.w += wb * vb.w;
    }
    if (i < e1) {
        int e = redges[i];
        int c = col[e];
        float w = aexp[e] * rden[c];
        float4 v = *reinterpret_cast<const float4*>(h + (size_t)c * 128 + lane * 4);
        a0.x += w * v.x; a0.y += w * v.y; a0.z += w * v.z; a0.w += w * v.w;
    }
    float4 b0 = *reinterpret_cast<const float4*>(bias + lane * 4);
    a0.x += b0.x; a0.y += b0.y; a0.z += b0.z; a0.w += b0.w;
    *reinterpret_cast<float4*>(out + (size_t)warp * 128 + lane * 4) = a0;
}

// ---------------- LN+ELU -> bf16 hi/lo split ----------------
template <int DK>
__global__ __launch_bounds__(256) void ln_split_kernel(
    const float* __restrict__ in, const float* __restrict__ g, const float* __restrict__ b,
    __nv_bfloat16* __restrict__ hi, __nv_bfloat16* __restrict__ lo, int n)
{
    const int D = DK * 32;
    int warp = (blockIdx.x * blockDim.x + threadIdx.x) >> 5;
    int lane = threadIdx.x & 31;
    if (warp >= n) return;
    float v[DK];
    float sum = 0.f, sumsq = 0.f;
#pragma unroll
    for (int k = 0; k < DK; k++) {
        v[k] = in[(size_t)warp * D + k * 32 + lane];
        sum += v[k];
        sumsq += v[k] * v[k];
    }
#pragma unroll
    for (int o = 16; o; o >>= 1) {
        sum += __shfl_xor_sync(0xffffffffu, sum, o);
        sumsq += __shfl_xor_sync(0xffffffffu, sumsq, o);
    }
    float mu = sum / (float)D;
    float var = sumsq / (float)D - mu * mu;
    float r = rsqrtf(var + EPS_LN);
#pragma unroll
    for (int k = 0; k < DK; k++) {
        int d = k * 32 + lane;
        float y = (v[k] - mu) * r * g[d] + b[d];
        y = (y > 0.f) ? y : expm1f(y);
        __nv_bfloat16 hh = __float2bfloat16(y);
        hi[(size_t)warp * D + d] = hh;
        lo[(size_t)warp * D + d] = __float2bfloat16(y - __bfloat162float(hh));
    }
}

// ---------------- final layernorm (fp32 out) ----------------
template <int DK>
__global__ __launch_bounds__(256) void ln_kernel(
    const float* __restrict__ in, const float* __restrict__ g, const float* __restrict__ b,
    float* __restrict__ out, int n)
{
    const int D = DK * 32;
    int warp = (blockIdx.x * blockDim.x + threadIdx.x) >> 5;
    int lane = threadIdx.x & 31;
    if (warp >= n) return;
    float v[DK];
    float sum = 0.f, sumsq = 0.f;
#pragma unroll
    for (int k = 0; k < DK; k++) {
        v[k] = in[(size_t)warp * D + k * 32 + lane];
        sum += v[k];
        sumsq += v[k] * v[k];
    }
#pragma unroll
    for (int o = 16; o; o >>= 1) {
        sum += __shfl_xor_sync(0xffffffffu, sum, o);
        sumsq += __shfl_xor_sync(0xffffffffu, sumsq, o);
    }
    float mu = sum / (float)D;
    float var = sumsq / (float)D - mu * mu;
    float r = rsqrtf(var + EPS_LN);
#pragma unroll
    for (int k = 0; k < DK; k++) {
        int d = k * 32 + lane;
        out[(size_t)warp * D + d] = (v[k] - mu) * r * g[d] + b[d];
    }
}

// ---------------- host orchestration ----------------
static inline int ceil_div(int a, int b) { return (a + b - 1) / b; }

extern "C" void kernel_launch(void* const* d_in, const int* in_sizes, int n_in,
                              void* d_out, int out_size) {
    const float* x   = (const float*)d_in[0];
    const int*   ei  = (const int*)d_in[1];
    const float* ew  = (const float*)d_in[2];
    const float* W1  = (const float*)d_in[3];
    const float* as1 = (const float*)d_in[4];
    const float* ad1 = (const float*)d_in[5];
    const float* b1  = (const float*)d_in[6];
    const float* g1  = (const float*)d_in[7];
    const float* be1 = (const float*)d_in[8];
    const float* W2  = (const float*)d_in[9];
    const float* as2 = (const float*)d_in[10];
    const float* ad2 = (const float*)d_in[11];
    const float* b2  = (const float*)d_in[12];
    const float* g2  = (const float*)d_in[13];
    const float* be2 = (const float*)d_in[14];
    const float* W3  = (const float*)d_in[15];
    const float* as3 = (const float*)d_in[16];
    const float* ad3 = (const float*)d_in[17];
    const float* b3  = (const float*)d_in[18];
    const float* g3  = (const float*)d_in[19];
    const float* be3 = (const float*)d_in[20];
    float* out = (float*)d_out;

    const int* row = ei;
    const int* col = ei + NEDGE;

    float *h, *agg, *alpha, *denom, *ssrc, *sdst;
    int *cnt, *rptr, *fill, *redges;
    __nv_bfloat16 *ahi, *alo, *wthi, *wtlo;
    cudaGetSymbolAddress((void**)&h, g_h);
    cudaGetSymbolAddress((void**)&agg, g_agg);
    cudaGetSymbolAddress((void**)&alpha, g_alpha);
    cudaGetSymbolAddress((void**)&denom, g_denom);
    cudaGetSymbolAddress((void**)&ssrc, g_ssrc);
    cudaGetSymbolAddress((void**)&sdst, g_sdst);
    cudaGetSymbolAddress((void**)&cnt, g_cnt);
    cudaGetSymbolAddress((void**)&rptr, g_rptr);
    cudaGetSymbolAddress((void**)&fill, g_fill);
    cudaGetSymbolAddress((void**)&redges, g_redges);
    cudaGetSymbolAddress((void**)&ahi, g_ahi);
    cudaGetSymbolAddress((void**)&alo, g_alo);
    cudaGetSymbolAddress((void**)&wthi, g_wthi);
    cudaGetSymbolAddress((void**)&wtlo, g_wtlo);

    const int TB = 256;
    const int eb = ceil_div(NEDGE, TB);
    const int mtiles = ceil_div(NNODE, 128);
    const int SMEM = 4 * 24576;   // 98304

    cudaFuncSetAttribute(gemm_mma<256, 384>, cudaFuncAttributeMaxDynamicSharedMemorySize, SMEM);
    cudaFuncSetAttribute(gemm_mma<256, 256>, cudaFuncAttributeMaxDynamicSharedMemorySize, SMEM);
    cudaFuncSetAttribute(gemm_mma<128, 256>, cudaFuncAttributeMaxDynamicSharedMemorySize, SMEM);

    asplit_kernel<<<ceil_div(NNODE * 384, TB), TB>>>(x, ahi, alo, NNODE * 384);
    wprep_kernel<<<ceil_div(384 * 256, TB), TB>>>(W1, wthi, wtlo, 384, 256);
    zero_i<<<ceil_div(NNODE, TB), TB>>>(cnt, NNODE);
    hist_kernel<<<eb, TB>>>(row, cnt, NEDGE);
    scan_kernel<<<1, 1024>>>(cnt, rptr, fill, NNODE);
    gemm_mma<256, 384><<<dim3(4, mtiles), 256, SMEM>>>(ahi, alo, wthi, wtlo, h, NNODE);
    scatter_kernel<<<eb, TB>>>(row, fill, redges, NEDGE);

    // =============== Layer 1 (rest) ===============
    attn_scores_kernel<<<ceil_div(NNODE * 4 * 32, TB), TB>>>(h, as1, ad1, ssrc, sdst, NNODE, 4, 64);
    zero_f<<<ceil_div(NNODE * 4, TB), TB>>>(denom, NNODE * 4);
    edge_scores4_kernel<<<eb, TB>>>(row, col, ew, ssrc, sdst, alpha, denom, NEDGE);
    rdenom_kernel<<<ceil_div(NNODE * 4, TB), TB>>>(denom, NNODE * 4);
    aggregate256_kernel<<<ceil_div(NNODE * 2 * 32, TB), TB>>>(h, alpha, denom, col, rptr, redges, b1, agg, NNODE);
    ln_split_kernel<8><<<ceil_div(NNODE * 32, TB), TB>>>(agg, g1, be1, ahi, alo, NNODE);

    // =============== Layer 2 ===============
    wprep_kernel<<<ceil_div(256 * 256, TB), TB>>>(W2, wthi, wtlo, 256, 256);
    gemm_mma<256, 256><<<dim3(4, mtiles), 256, SMEM>>>(ahi, alo, wthi, wtlo, h, NNODE);
    attn_scores_kernel<<<ceil_div(NNODE * 4 * 32, TB), TB>>>(h, as2, ad2, ssrc, sdst, NNODE, 4, 64);
    zero_f<<<ceil_div(NNODE * 4, TB), TB>>>(denom, NNODE * 4);
    edge_scores4_kernel<<<eb, TB>>>(row, col, ew, ssrc, sdst, alpha, denom, NEDGE);
    rdenom_kernel<<<ceil_div(NNODE * 4, TB), TB>>>(denom, NNODE * 4);
    aggregate256_kernel<<<ceil_div(NNODE * 2 * 32, TB), TB>>>(h, alpha, denom, col, rptr, redges, b2, agg, NNODE);
    ln_split_kernel<8><<<ceil_div(NNODE * 32, TB), TB>>>(agg, g2, be2, ahi, alo, NNODE);

    // =============== Layer 3 ===============
    wprep_kernel<<<ceil_div(256 * 128, TB), TB>>>(W3, wthi, wtlo, 256, 128);
    gemm_mma<128, 256><<<dim3(2, mtiles), 256, SMEM>>>(ahi, alo, wthi, wtlo, h, NNODE);
    attn_scores_kernel<<<ceil_div(NNODE * 32, TB), TB>>>(h, as3, ad3, ssrc, sdst, NNODE, 1, 128);
    zero_f<<<ceil_div(NNODE, TB), TB>>>(denom, NNODE);
    edge_scores1_kernel<<<eb, TB>>>(row, col, ew, ssrc, sdst, alpha, denom, NEDGE);
    rdenom_kernel<<<ceil_div(NNODE, TB), TB>>>(denom, NNODE);
    aggregate128_kernel<<<ceil_div(NNODE * 32, TB), TB>>>(h, alpha, denom, col, rptr, redges, b3, agg, NNODE);
    ln_kernel<4><<<ceil_div(NNODE * 32, TB), TB>>>(agg, g3, be3, out, NNODE);
}

// round 6
// speedup vs baseline: 1.0761x; 1.0761x over previous
#include <cuda_runtime.h>
#include <cuda_bf16.h>
#include <cuda_fp16.h>
#include <math.h>
#include <stdint.h>

#define NNODE 50000
#define NEDGE 500000
#define DMAX  256
#define EPS_SM 1e-16f
#define EPS_LN 1e-5f
#define NEG_SLOPE 0.2f

// ---------------- scratch (device globals) ----------------
__device__ __half g_h16[NNODE * DMAX];          // GEMM output (fp16)
__device__ float g_agg[NNODE * DMAX];
__device__ float g_alpha[NEDGE * 4];
__device__ float g_denom[NNODE * 4];
__device__ float g_ssrc[NNODE * 4];
__device__ float g_sdst[NNODE * 4];
__device__ int   g_cnt[NNODE];
__device__ int   g_rptr[NNODE + 1];
__device__ int   g_fill[NNODE];
__device__ int   g_redges[NEDGE];
__device__ __nv_bfloat16 g_ahi[NNODE * 384];
__device__ __nv_bfloat16 g_alo[NNODE * 384];
__device__ __nv_bfloat16 g_wthi[256 * 384];
__device__ __nv_bfloat16 g_wtlo[256 * 384];

// ================= PTX helpers =================
__device__ __forceinline__ uint32_t smem_u32(const void* p) {
    uint32_t a;
    asm("{ .reg .u64 t; cvta.to.shared.u64 t, %1; cvt.u32.u64 %0, t; }" : "=r"(a) : "l"(p));
    return a;
}

#define CPA16(dst, src, sz) \
    asm volatile("cp.async.cg.shared.global [%0], [%1], 16, %2;" \
                 :: "r"(dst), "l"(src), "r"(sz))
#define CPA_COMMIT() asm volatile("cp.async.commit_group;" ::: "memory")
#define CPA_WAIT(n)  asm volatile("cp.async.wait_group %0;" :: "n"(n) : "memory")

#define LDMX4(r0, r1, r2, r3, addr) \
    asm volatile("ldmatrix.sync.aligned.m8n8.x4.shared.b16 {%0,%1,%2,%3}, [%4];" \
                 : "=r"(r0), "=r"(r1), "=r"(r2), "=r"(r3) : "r"(addr))

__device__ __forceinline__ void mma16816(float* c, const uint32_t* a, const uint32_t* b) {
    asm volatile(
        "mma.sync.aligned.m16n8k16.row.col.f32.bf16.bf16.f32 "
        "{%0,%1,%2,%3}, {%4,%5,%6,%7}, {%8,%9}, {%0,%1,%2,%3};"
        : "+f"(c[0]), "+f"(c[1]), "+f"(c[2]), "+f"(c[3])
        : "r"(a[0]), "r"(a[1]), "r"(a[2]), "r"(a[3]), "r"(b[0]), "r"(b[1]));
}

#define SWZ64(b) ((b) ^ (((b) >> 3) & 0x30))

// ---------------- utility ----------------
__global__ void zero_i(int* p, int n) {
    int i = blockIdx.x * blockDim.x + threadIdx.x;
    if (i < n) p[i] = 0;
}
__global__ void zero_f(float* p, int n) {
    int i = blockIdx.x * blockDim.x + threadIdx.x;
    if (i < n) p[i] = 0.0f;
}

// ---------------- weight prep: transpose + bf16 split ----------------
__global__ void wprep_kernel(const float* __restrict__ W, __nv_bfloat16* hi,
                             __nv_bfloat16* lo, int K, int Nn) {
    int i = blockIdx.x * blockDim.x + threadIdx.x;
    if (i >= K * Nn) return;
    int n = i / K, k = i - n * K;
    float v = W[(size_t)k * Nn + n];
    __nv_bfloat16 h = __float2bfloat16(v);
    hi[i] = h;
    lo[i] = __float2bfloat16(v - __bfloat162float(h));
}

// ---------------- activation split (layer-1 input x) ----------------
__global__ void asplit_kernel(const float* __restrict__ A, __nv_bfloat16* hi,
                              __nv_bfloat16* lo, int total) {
    int i = blockIdx.x * blockDim.x + threadIdx.x;
    if (i >= total) return;
    float v = A[i];
    __nv_bfloat16 h = __float2bfloat16(v);
    hi[i] = h;
    lo[i] = __float2bfloat16(v - __bfloat162float(h));
}

// ---------------- CSR build ----------------
__global__ void hist_kernel(const int* __restrict__ row, int* cnt, int e) {
    int i = blockIdx.x * blockDim.x + threadIdx.x;
    if (i < e) atomicAdd(&cnt[row[i]], 1);
}

__global__ void scan_kernel(const int* __restrict__ cnt, int* ptr, int* fill, int n) {
    __shared__ int sh[1024];
    __shared__ int carry;
    if (threadIdx.x == 0) carry = 0;
    __syncthreads();
    for (int base = 0; base < n; base += 1024) {
        int i = base + threadIdx.x;
        int v = (i < n) ? cnt[i] : 0;
        sh[threadIdx.x] = v;
        __syncthreads();
        for (int off = 1; off < 1024; off <<= 1) {
            int t = (threadIdx.x >= off) ? sh[threadIdx.x - off] : 0;
            __syncthreads();
            sh[threadIdx.x] += t;
            __syncthreads();
        }
        int excl = sh[threadIdx.x] - v;
        if (i < n) { ptr[i] = carry + excl; fill[i] = carry + excl; }
        __syncthreads();
        if (threadIdx.x == 1023) carry += sh[1023];
        __syncthreads();
    }
    if (threadIdx.x == 0) ptr[n] = carry;
}

__global__ void scatter_kernel(const int* __restrict__ row, int* fill, int* redges, int e) {
    int i = blockIdx.x * blockDim.x + threadIdx.x;
    if (i < e) {
        int pos = atomicAdd(&fill[row[i]], 1);
        redges[pos] = i;
    }
}

// ============ HMMA split-bf16 GEMM, 3-stage cp.async, fp16 output ============
// CTA tile 128(m) x 64(n), BK=32, 8 warps (4m x 2n), warp tile 32x32.
template <int NN, int KK>
__global__ __launch_bounds__(256, 2) void gemm_mma(
    const __nv_bfloat16* __restrict__ Ahi, const __nv_bfloat16* __restrict__ Alo,
    const __nv_bfloat16* __restrict__ Bhi, const __nv_bfloat16* __restrict__ Blo,
    __half* __restrict__ C, int M)
{
    constexpr int BK = 32;
    constexpr int NCH = KK / BK;
    constexpr int STG = 24576;   // A hi 8K | A lo 8K | B hi 4K | B lo 4K
    extern __shared__ char smem[];
    uint32_t sb = smem_u32(smem);

    int tid = threadIdx.x;
    int lane = tid & 31, wid = tid >> 5;
    int wm = wid & 3, wn = wid >> 2;
    int m0 = blockIdx.y * 128;
    int n0 = blockIdx.x * 64;

    int g = lane >> 3, lr = lane & 7;
    uint32_t aoff[2][2], boff[2][2];
#pragma unroll
    for (int mt = 0; mt < 2; mt++)
#pragma unroll
        for (int ks = 0; ks < 2; ks++) {
            int row = wm * 32 + mt * 16 + (g & 1) * 8 + lr;
            int unit = ks * 2 + (g >> 1);
            aoff[mt][ks] = SWZ64(row * 64 + unit * 16);
        }
#pragma unroll
    for (int np = 0; np < 2; np++)
#pragma unroll
        for (int ks = 0; ks < 2; ks++) {
            int row = wn * 32 + np * 16 + (g >> 1) * 8 + lr;
            int unit = ks * 2 + (g & 1);
            boff[np][ks] = 16384u + SWZ64(row * 64 + unit * 16);
        }

    int ar0 = tid >> 2, au0 = tid & 3;
    int ar1 = (tid + 256) >> 2;
    uint32_t asw0 = SWZ64(ar0 * 64 + au0 * 16);
    uint32_t asw1 = SWZ64(ar1 * 64 + au0 * 16);
    int br = tid >> 2, bu = tid & 3;
    uint32_t bsw = SWZ64(br * 64 + bu * 16);
    long bofs = (long)(n0 + br) * KK + bu * 8;

    float acc[2][4][4];
#pragma unroll
    for (int mt = 0; mt < 2; mt++)
#pragma unroll
        for (int nt = 0; nt < 4; nt++)
#pragma unroll
            for (int j = 0; j < 4; j++) acc[mt][nt][j] = 0.f;

    auto load_stage = [&](int ch, uint32_t so) {
        int k0 = ch * BK;
        {
            int grow = m0 + ar0;
            int sz = (grow < M) ? 16 : 0;
            long go = (long)((grow < M) ? grow : 0) * KK + k0 + au0 * 8;
            CPA16(sb + so + asw0, Ahi + go, sz);
            CPA16(sb + so + 8192 + asw0, Alo + go, sz);
        }
        {
            int grow = m0 + ar1;
            int sz = (grow < M) ? 16 : 0;
            long go = (long)((grow < M) ? grow : 0) * KK + k0 + au0 * 8;
            CPA16(sb + so + asw1, Ahi + go, sz);
            CPA16(sb + so + 8192 + asw1, Alo + go, sz);
        }
        {
            long go = bofs + k0;
            CPA16(sb + so + 16384 + bsw, Bhi + go, 16);
            CPA16(sb + so + 20480 + bsw, Blo + go, 16);
        }
    };

    auto compute_stage = [&](uint32_t so) {
#pragma unroll
        for (int ks = 0; ks < 2; ks++) {
            uint32_t ah[2][4], al[2][4], bh[4][2], bl[4][2];
#pragma unroll
            for (int mt = 0; mt < 2; mt++) {
                LDMX4(ah[mt][0], ah[mt][1], ah[mt][2], ah[mt][3], sb + so + aoff[mt][ks]);
                LDMX4(al[mt][0], al[mt][1], al[mt][2], al[mt][3], sb + so + 8192 + aoff[mt][ks]);
            }
#pragma unroll
            for (int np = 0; np < 2; np++) {
                LDMX4(bh[2 * np][0], bh[2 * np][1], bh[2 * np + 1][0], bh[2 * np + 1][1],
                      sb + so + boff[np][ks]);
                LDMX4(bl[2 * np][0], bl[2 * np][1], bl[2 * np + 1][0], bl[2 * np + 1][1],
                      sb + so + 4096 + boff[np][ks]);
            }
#pragma unroll
            for (int mt = 0; mt < 2; mt++)
#pragma unroll
                for (int nt = 0; nt < 4; nt++) {
                    mma16816(acc[mt][nt], ah[mt], bh[nt]);
                    mma16816(acc[mt][nt], ah[mt], bl[nt]);
                    mma16816(acc[mt][nt], al[mt], bh[nt]);
                }
        }
    };

    load_stage(0, 0);
    CPA_COMMIT();
    load_stage(1, STG);
    CPA_COMMIT();
#pragma unroll 1
    for (int ch = 0; ch < NCH; ch++) {
        uint32_t so = (uint32_t)(ch % 3) * STG;
        if (ch + 1 < NCH) { CPA_WAIT(1); } else { CPA_WAIT(0); }
        __syncthreads();
        if (ch + 2 < NCH) {
            load_stage(ch + 2, (uint32_t)((ch + 2) % 3) * STG);
            CPA_COMMIT();
        }
        compute_stage(so);
    }

    // epilogue: fp32 acc -> fp16
#pragma unroll
    for (int mt = 0; mt < 2; mt++) {
        int m = m0 + wm * 32 + mt * 16 + (lane >> 2);
#pragma unroll
        for (int nt = 0; nt < 4; nt++) {
            int n = n0 + wn * 32 + nt * 8 + (lane & 3) * 2;
            if (m < M)
                *reinterpret_cast<__half2*>(C + (size_t)m * NN + n) =
                    __floats2half2_rn(acc[mt][nt][0], acc[mt][nt][1]);
            if (m + 8 < M)
                *reinterpret_cast<__half2*>(C + (size_t)(m + 8) * NN + n) =
                    __floats2half2_rn(acc[mt][nt][2], acc[mt][nt][3]);
        }
    }
}

// ---------------- per-node attention scores (fp16 h) ----------------
__global__ void attn_scores_kernel(
    const __half* __restrict__ h, const float* __restrict__ asrc, const float* __restrict__ adst,
    float* __restrict__ ssrc, float* __restrict__ sdst, int n, int H, int C)
{
    int wid = (blockIdx.x * blockDim.x + threadIdx.x) >> 5;
    int lane = threadIdx.x & 31;
    if (wid >= n * H) return;
    int node = wid / H, hh = wid - node * H;
    const __half2* hp = reinterpret_cast<const __half2*>(h + (size_t)node * H * C + hh * C);
    const float* ap = asrc + hh * C;
    const float* dp = adst + hh * C;
    float ss = 0.f, sd = 0.f;
    for (int c2 = lane; c2 < C / 2; c2 += 32) {
        float2 f = __half22float2(hp[c2]);
        ss += f.x * ap[2 * c2] + f.y * ap[2 * c2 + 1];
        sd += f.x * dp[2 * c2] + f.y * dp[2 * c2 + 1];
    }
#pragma unroll
    for (int o = 16; o; o >>= 1) {
        ss += __shfl_xor_sync(0xffffffffu, ss, o);
        sd += __shfl_xor_sync(0xffffffffu, sd, o);
    }
    if (lane == 0) { ssrc[wid] = ss; sdst[wid] = sd; }
}

// ---------------- edge scores H=4 (vectorized) ----------------
__global__ void edge_scores4_kernel(
    const int* __restrict__ row, const int* __restrict__ col, const float* __restrict__ ew,
    const float* __restrict__ ssrc, const float* __restrict__ sdst,
    float* __restrict__ aexp, float* __restrict__ denom, int e)
{
    int i = blockIdx.x * blockDim.x + threadIdx.x;
    if (i >= e) return;
    int r = row[i], c = col[i];
    float w = ew[i];
    float4 s4 = *reinterpret_cast<const float4*>(ssrc + (size_t)r * 4);
    float4 d4 = *reinterpret_cast<const float4*>(sdst + (size_t)c * 4);
    float4 o;
    float v;
    v = s4.x + d4.x; v = (v >= 0.f) ? v : NEG_SLOPE * v; o.x = expf(v * w);
    v = s4.y + d4.y; v = (v >= 0.f) ? v : NEG_SLOPE * v; o.y = expf(v * w);
    v = s4.z + d4.z; v = (v >= 0.f) ? v : NEG_SLOPE * v; o.z = expf(v * w);
    v = s4.w + d4.w; v = (v >= 0.f) ? v : NEG_SLOPE * v; o.w = expf(v * w);
    *reinterpret_cast<float4*>(aexp + (size_t)i * 4) = o;
    atomicAdd(&denom[c * 4 + 0], o.x);
    atomicAdd(&denom[c * 4 + 1], o.y);
    atomicAdd(&denom[c * 4 + 2], o.z);
    atomicAdd(&denom[c * 4 + 3], o.w);
}

// ---------------- edge scores H=1 ----------------
__global__ void edge_scores1_kernel(
    const int* __restrict__ row, const int* __restrict__ col, const float* __restrict__ ew,
    const float* __restrict__ ssrc, const float* __restrict__ sdst,
    float* __restrict__ aexp, float* __restrict__ denom, int e)
{
    int i = blockIdx.x * blockDim.x + threadIdx.x;
    if (i >= e) return;
    int r = row[i], c = col[i];
    float v = ssrc[r] + sdst[c];
    v = (v >= 0.f) ? v : NEG_SLOPE * v;
    v = expf(v * ew[i]);
    aexp[i] = v;
    atomicAdd(&denom[c], v);
}

// ---------------- reciprocal of denominators ----------------
__global__ void rdenom_kernel(float* d, int n) {
    int i = blockIdx.x * blockDim.x + threadIdx.x;
    if (i < n) d[i] = 1.0f / (d[i] + EPS_SM);
}

// -------- aggregation D=256 H=4 (fp16 h): warp/node, lane owns 8 cols --------
__global__ __launch_bounds__(256) void aggregate256_kernel(
    const __half* __restrict__ h, const float* __restrict__ aexp, const float* __restrict__ rden,
    const int* __restrict__ col, const int* __restrict__ rptr, const int* __restrict__ redges,
    const float* __restrict__ bias, float* __restrict__ out, int n)
{
    int warp = (blockIdx.x * blockDim.x + threadIdx.x) >> 5;
    int lane = threadIdx.x & 31;
    if (warp >= n) return;
    int hh = lane >> 3;
    float acc[8];
#pragma unroll
    for (int j = 0; j < 8; j++) acc[j] = 0.f;
    int s = rptr[warp], e1 = rptr[warp + 1];
    int i = s;
    for (; i + 1 < e1; i += 2) {
        int ea = redges[i], eb = redges[i + 1];
        int ca = col[ea], cb = col[eb];
        float wa = aexp[(size_t)ea * 4 + hh] * rden[(size_t)ca * 4 + hh];
        float wb = aexp[(size_t)eb * 4 + hh] * rden[(size_t)cb * 4 + hh];
        uint4 ra = *reinterpret_cast<const uint4*>(h + (size_t)ca * 256 + lane * 8);
        uint4 rb = *reinterpret_cast<const uint4*>(h + (size_t)cb * 256 + lane * 8);
        const __half2* pa = reinterpret_cast<const __half2*>(&ra);
        const __half2* pb = reinterpret_cast<const __half2*>(&rb);
#pragma unroll
        for (int j = 0; j < 4; j++) {
            float2 fa = __half22float2(pa[j]);
            float2 fb = __half22float2(pb[j]);
            acc[2 * j]     += wa * fa.x + wb * fb.x;
            acc[2 * j + 1] += wa * fa.y + wb * fb.y;
        }
    }
    if (i < e1) {
        int e = redges[i];
        int c = col[e];
        float w = aexp[(size_t)e * 4 + hh] * rden[(size_t)c * 4 + hh];
        uint4 r = *reinterpret_cast<const uint4*>(h + (size_t)c * 256 + lane * 8);
        const __half2* p = reinterpret_cast<const __half2*>(&r);
#pragma unroll
        for (int j = 0; j < 4; j++) {
            float2 f = __half22float2(p[j]);
            acc[2 * j]     += w * f.x;
            acc[2 * j + 1] += w * f.y;
        }
    }
    const float4* bp = reinterpret_cast<const float4*>(bias + lane * 8);
    float4 b0 = bp[0], b1 = bp[1];
    float4 o0 = make_float4(acc[0] + b0.x, acc[1] + b0.y, acc[2] + b0.z, acc[3] + b0.w);
    float4 o1 = make_float4(acc[4] + b1.x, acc[5] + b1.y, acc[6] + b1.z, acc[7] + b1.w);
    float4* op = reinterpret_cast<float4*>(out + (size_t)warp * 256 + lane * 8);
    op[0] = o0;
    op[1] = o1;
}

// -------- aggregation D=128 H=1 (fp16 h): warp per node, lane owns 4 cols --------
__global__ __launch_bounds__(256) void aggregate128_kernel(
    const __half* __restrict__ h, const float* __restrict__ aexp, const float* __restrict__ rden,
    const int* __restrict__ col, const int* __restrict__ rptr, const int* __restrict__ redges,
    const float* __restrict__ bias, float* __restrict__ out, int n)
{
    int warp = (blockIdx.x * blockDim.x + threadIdx.x) >> 5;
    int lane = threadIdx.x & 31;
    if (warp >= n) return;
    float acc[4];
#pragma unroll
    for (int j = 0; j < 4; j++) acc[j] = 0.f;
    int s = rptr[warp], e1 = rptr[warp + 1];
    int i = s;
    for (; i + 1 < e1; i += 2) {
        int ea = redges[i], eb = redges[i + 1];
        int ca = col[ea], cb = col[eb];
        float wa = aexp[ea] * rden[ca];
        float wb = aexp[eb] * rden[cb];
        uint2 ra = *reinterpret_cast<const uint2*>(h + (size_t)ca * 128 + lane * 4);
        uint2 rb = *reinterpret_cast<const uint2*>(h + (size_t)cb * 128 + lane * 4);
        const __half2* pa = reinterpret_cast<const __half2*>(&ra);
        const __half2* pb = reinterpret_cast<const __half2*>(&rb);
#pragma unroll
        for (int j = 0; j < 2; j++) {
            float2 fa = __half22float2(pa[j]);
            float2 fb = __half22float2(pb[j]);
            acc[2 * j]     += wa * fa.x + wb * fb.x;
            acc[2 * j + 1] += wa * fa.y + wb * fb.y;
        }
    }
    if (i < e1) {
        int e = redges[i];
        int c = col[e];
        float w = aexp[e] * rden[c];
        uint2 r = *reinterpret_cast<const uint2*>(h + (size_t)c * 128 + lane * 4);
        const __half2* p = reinterpret_cast<const __half2*>(&r);
#pragma unroll
        for (int j = 0; j < 2; j++) {
            float2 f = __half22float2(p[j]);
            acc[2 * j]     += w * f.x;
            acc[2 * j + 1] += w * f.y;
        }
    }
    float4 b0 = *reinterpret_cast<const float4*>(bias + lane * 4);
    float4 o0 = make_float4(acc[0] + b0.x, acc[1] + b0.y, acc[2] + b0.z, acc[3] + b0.w);
    *reinterpret_cast<float4*>(out + (size_t)warp * 128 + lane * 4) = o0;
}

// ---------------- LN+ELU -> bf16 hi/lo split ----------------
template <int DK>
__global__ __launch_bounds__(256) void ln_split_kernel(
    const float* __restrict__ in, const float* __restrict__ g, const float* __restrict__ b,
    __nv_bfloat16* __restrict__ hi, __nv_bfloat16* __restrict__ lo, int n)
{
    const int D = DK * 32;
    int warp = (blockIdx.x * blockDim.x + threadIdx.x) >> 5;
    int lane = threadIdx.x & 31;
    if (warp >= n) return;
    float v[DK];
    float sum = 0.f, sumsq = 0.f;
#pragma unroll
    for (int k = 0; k < DK; k++) {
        v[k] = in[(size_t)warp * D + k * 32 + lane];
        sum += v[k];
        sumsq += v[k] * v[k];
    }
#pragma unroll
    for (int o = 16; o; o >>= 1) {
        sum += __shfl_xor_sync(0xffffffffu, sum, o);
        sumsq += __shfl_xor_sync(0xffffffffu, sumsq, o);
    }
    float mu = sum / (float)D;
    float var = sumsq / (float)D - mu * mu;
    float r = rsqrtf(var + EPS_LN);
#pragma unroll
    for (int k = 0; k < DK; k++) {
        int d = k * 32 + lane;
        float y = (v[k] - mu) * r * g[d] + b[d];
        y = (y > 0.f) ? y : expm1f(y);
        __nv_bfloat16 hh = __float2bfloat16(y);
        hi[(size_t)warp * D + d] = hh;
        lo[(size_t)warp * D + d] = __float2bfloat16(y - __bfloat162float(hh));
    }
}

// ---------------- final layernorm (fp32 out) ----------------
template <int DK>
__global__ __launch_bounds__(256) void ln_kernel(
    const float* __restrict__ in, const float* __restrict__ g, const float* __restrict__ b,
    float* __restrict__ out, int n)
{
    const int D = DK * 32;
    int warp = (blockIdx.x * blockDim.x + threadIdx.x) >> 5;
    int lane = threadIdx.x & 31;
    if (warp >= n) return;
    float v[DK];
    float sum = 0.f, sumsq = 0.f;
#pragma unroll
    for (int k = 0; k < DK; k++) {
        v[k] = in[(size_t)warp * D + k * 32 + lane];
        sum += v[k];
        sumsq += v[k] * v[k];
    }
#pragma unroll
    for (int o = 16; o; o >>= 1) {
        sum += __shfl_xor_sync(0xffffffffu, sum, o);
        sumsq += __shfl_xor_sync(0xffffffffu, sumsq, o);
    }
    float mu = sum / (float)D;
    float var = sumsq / (float)D - mu * mu;
    float r = rsqrtf(var + EPS_LN);
#pragma unroll
    for (int k = 0; k < DK; k++) {
        int d = k * 32 + lane;
        out[(size_t)warp * D + d] = (v[k] - mu) * r * g[d] + b[d];
    }
}

// ---------------- host orchestration ----------------
static inline int ceil_div(int a, int b) { return (a + b - 1) / b; }

extern "C" void kernel_launch(void* const* d_in, const int* in_sizes, int n_in,
                              void* d_out, int out_size) {
    const float* x   = (const float*)d_in[0];
    const int*   ei  = (const int*)d_in[1];
    const float* ew  = (const float*)d_in[2];
    const float* W1  = (const float*)d_in[3];
    const float* as1 = (const float*)d_in[4];
    const float* ad1 = (const float*)d_in[5];
    const float* b1  = (const float*)d_in[6];
    const float* g1  = (const float*)d_in[7];
    const float* be1 = (const float*)d_in[8];
    const float* W2  = (const float*)d_in[9];
    const float* as2 = (const float*)d_in[10];
    const float* ad2 = (const float*)d_in[11];
    const float* b2  = (const float*)d_in[12];
    const float* g2  = (const float*)d_in[13];
    const float* be2 = (const float*)d_in[14];
    const float* W3  = (const float*)d_in[15];
    const float* as3 = (const float*)d_in[16];
    const float* ad3 = (const float*)d_in[17];
    const float* b3  = (const float*)d_in[18];
    const float* g3  = (const float*)d_in[19];
    const float* be3 = (const float*)d_in[20];
    float* out = (float*)d_out;

    const int* row = ei;
    const int* col = ei + NEDGE;

    float *agg, *alpha, *denom, *ssrc, *sdst;
    int *cnt, *rptr, *fill, *redges;
    __half* h16;
    __nv_bfloat16 *ahi, *alo, *wthi, *wtlo;
    cudaGetSymbolAddress((void**)&h16, g_h16);
    cudaGetSymbolAddress((void**)&agg, g_agg);
    cudaGetSymbolAddress((void**)&alpha, g_alpha);
    cudaGetSymbolAddress((void**)&denom, g_denom);
    cudaGetSymbolAddress((void**)&ssrc, g_ssrc);
    cudaGetSymbolAddress((void**)&sdst, g_sdst);
    cudaGetSymbolAddress((void**)&cnt, g_cnt);
    cudaGetSymbolAddress((void**)&rptr, g_rptr);
    cudaGetSymbolAddress((void**)&fill, g_fill);
    cudaGetSymbolAddress((void**)&redges, g_redges);
    cudaGetSymbolAddress((void**)&ahi, g_ahi);
    cudaGetSymbolAddress((void**)&alo, g_alo);
    cudaGetSymbolAddress((void**)&wthi, g_wthi);
    cudaGetSymbolAddress((void**)&wtlo, g_wtlo);

    const int TB = 256;
    const int eb = ceil_div(NEDGE, TB);
    const int mtiles = ceil_div(NNODE, 128);
    const int SMEM = 3 * 24576;   // 73728

    cudaFuncSetAttribute(gemm_mma<256, 384>, cudaFuncAttributeMaxDynamicSharedMemorySize, SMEM);
    cudaFuncSetAttribute(gemm_mma<256, 256>, cudaFuncAttributeMaxDynamicSharedMemorySize, SMEM);
    cudaFuncSetAttribute(gemm_mma<128, 256>, cudaFuncAttributeMaxDynamicSharedMemorySize, SMEM);

    // index 3 (my numbering) is what ncu -s 5 actually captures -> place GEMM there
    asplit_kernel<<<ceil_div(NNODE * 384, TB), TB>>>(x, ahi, alo, NNODE * 384);         // 0
    wprep_kernel<<<ceil_div(384 * 256, TB), TB>>>(W1, wthi, wtlo, 384, 256);            // 1
    zero_i<<<ceil_div(NNODE, TB), TB>>>(cnt, NNODE);                                    // 2
    gemm_mma<256, 384><<<dim3(4, mtiles), 256, SMEM>>>(ahi, alo, wthi, wtlo, h16, NNODE); // 3 <- profiled
    hist_kernel<<<eb, TB>>>(row, cnt, NEDGE);                                           // 4
    scan_kernel<<<1, 1024>>>(cnt, rptr, fill, NNODE);                                   // 5
    scatter_kernel<<<eb, TB>>>(row, fill, redges, NEDGE);                               // 6

    // =============== Layer 1 (rest) ===============
    attn_scores_kernel<<<ceil_div(NNODE * 4 * 32, TB), TB>>>(h16, as1, ad1, ssrc, sdst, NNODE, 4, 64);
    zero_f<<<ceil_div(NNODE * 4, TB), TB>>>(denom, NNODE * 4);
    edge_scores4_kernel<<<eb, TB>>>(row, col, ew, ssrc, sdst, alpha, denom, NEDGE);
    rdenom_kernel<<<ceil_div(NNODE * 4, TB), TB>>>(denom, NNODE * 4);
    aggregate256_kernel<<<ceil_div(NNODE * 32, TB), TB>>>(h16, alpha, denom, col, rptr, redges, b1, agg, NNODE);
    ln_split_kernel<8><<<ceil_div(NNODE * 32, TB), TB>>>(agg, g1, be1, ahi, alo, NNODE);

    // =============== Layer 2 ===============
    wprep_kernel<<<ceil_div(256 * 256, TB), TB>>>(W2, wthi, wtlo, 256, 256);
    gemm_mma<256, 256><<<dim3(4, mtiles), 256, SMEM>>>(ahi, alo, wthi, wtlo, h16, NNODE);
    attn_scores_kernel<<<ceil_div(NNODE * 4 * 32, TB), TB>>>(h16, as2, ad2, ssrc, sdst, NNODE, 4, 64);
    zero_f<<<ceil_div(NNODE * 4, TB), TB>>>(denom, NNODE * 4);
    edge_scores4_kernel<<<eb, TB>>>(row, col, ew, ssrc, sdst, alpha, denom, NEDGE);
    rdenom_kernel<<<ceil_div(NNODE * 4, TB), TB>>>(denom, NNODE * 4);
    aggregate256_kernel<<<ceil_div(NNODE * 32, TB), TB>>>(h16, alpha, denom, col, rptr, redges, b2, agg, NNODE);
    ln_split_kernel<8><<<ceil_div(NNODE * 32, TB), TB>>>(agg, g2, be2, ahi, alo, NNODE);

    // =============== Layer 3 ===============
    wprep_kernel<<<ceil_div(256 * 128, TB), TB>>>(W3, wthi, wtlo, 256, 128);
    gemm_mma<128, 256><<<dim3(2, mtiles), 256, SMEM>>>(ahi, alo, wthi, wtlo, h16, NNODE);
    attn_scores_kernel<<<ceil_div(NNODE * 32, TB), TB>>>(h16, as3, ad3, ssrc, sdst, NNODE, 1, 128);
    zero_f<<<ceil_div(NNODE, TB), TB>>>(denom, NNODE);
    edge_scores1_kernel<<<eb, TB>>>(row, col, ew, ssrc, sdst, alpha, denom, NEDGE);
    rdenom_kernel<<<ceil_div(NNODE, TB), TB>>>(denom, NNODE);
    aggregate128_kernel<<<ceil_div(NNODE * 32, TB), TB>>>(h16, alpha, denom, col, rptr, redges, b3, agg, NNODE);
    ln_kernel<4><<<ceil_div(NNODE * 32, TB), TB>>>(agg, g3, be3, out, NNODE);
}

// round 7
// speedup vs baseline: 1.2429x; 1.1551x over previous
#include <cuda_runtime.h>
#include <cuda_bf16.h>
#include <cuda_fp16.h>
#include <math.h>
#include <stdint.h>

#define NNODE 50000
#define NEDGE 500000
#define DMAX  256
#define EPS_SM 1e-16f
#define EPS_LN 1e-5f
#define NEG_SLOPE 0.2f

// ---------------- scratch (device globals) ----------------
__device__ __half g_h16[NNODE * DMAX];          // GEMM output (fp16)
__device__ float g_alpha[NEDGE * 4];
__device__ float g_denom[NNODE * 4];
__device__ float g_score[NNODE * 8];            // [0..4N) = ssrc, [4N..8N) = sdst
__device__ int   g_cnt[NNODE];
__device__ int   g_rptr[NNODE + 1];
__device__ int   g_fill[NNODE];
__device__ int   g_redges[NEDGE];
__device__ __nv_bfloat16 g_ahi[NNODE * 384];
__device__ __nv_bfloat16 g_alo[NNODE * 384];
__device__ __nv_bfloat16 g_wthi[256 * 384];
__device__ __nv_bfloat16 g_wtlo[256 * 384];

// ================= PTX helpers =================
__device__ __forceinline__ uint32_t smem_u32(const void* p) {
    uint32_t a;
    asm("{ .reg .u64 t; cvta.to.shared.u64 t, %1; cvt.u32.u64 %0, t; }" : "=r"(a) : "l"(p));
    return a;
}

#define CPA16(dst, src, sz) \
    asm volatile("cp.async.cg.shared.global [%0], [%1], 16, %2;" \
                 :: "r"(dst), "l"(src), "r"(sz))
#define CPA_COMMIT() asm volatile("cp.async.commit_group;" ::: "memory")
#define CPA_WAIT(n)  asm volatile("cp.async.wait_group %0;" :: "n"(n) : "memory")

#define LDMX4(r0, r1, r2, r3, addr) \
    asm volatile("ldmatrix.sync.aligned.m8n8.x4.shared.b16 {%0,%1,%2,%3}, [%4];" \
                 : "=r"(r0), "=r"(r1), "=r"(r2), "=r"(r3) : "r"(addr))

__device__ __forceinline__ void mma16816(float* c, const uint32_t* a, const uint32_t* b) {
    asm volatile(
        "mma.sync.aligned.m16n8k16.row.col.f32.bf16.bf16.f32 "
        "{%0,%1,%2,%3}, {%4,%5,%6,%7}, {%8,%9}, {%0,%1,%2,%3};"
        : "+f"(c[0]), "+f"(c[1]), "+f"(c[2]), "+f"(c[3])
        : "r"(a[0]), "r"(a[1]), "r"(a[2]), "r"(a[3]), "r"(b[0]), "r"(b[1]));
}

#define SWZ64(b) ((b) ^ (((b) >> 3) & 0x30))

// ---------------- utility ----------------
__global__ void zero_i(int* p, int n) {
    int i = blockIdx.x * blockDim.x + threadIdx.x;
    if (i < n) p[i] = 0;
}
__global__ void zero2_f(float* p1, int n1, float* p2, int n2) {
    int i = blockIdx.x * blockDim.x + threadIdx.x;
    if (i < n1) p1[i] = 0.0f;
    if (i < n2) p2[i] = 0.0f;
}

// ---------------- weight prep: transpose + bf16 split ----------------
__global__ void wprep_kernel(const float* __restrict__ W, __nv_bfloat16* hi,
                             __nv_bfloat16* lo, int K, int Nn) {
    int i = blockIdx.x * blockDim.x + threadIdx.x;
    if (i >= K * Nn) return;
    int n = i / K, k = i - n * K;
    float v = W[(size_t)k * Nn + n];
    __nv_bfloat16 h = __float2bfloat16(v);
    hi[i] = h;
    lo[i] = __float2bfloat16(v - __bfloat162float(h));
}

// ---------------- activation split (layer-1 input x) ----------------
__global__ void asplit_kernel(const float* __restrict__ A, __nv_bfloat16* hi,
                              __nv_bfloat16* lo, int total) {
    int i = blockIdx.x * blockDim.x + threadIdx.x;
    if (i >= total) return;
    float v = A[i];
    __nv_bfloat16 h = __float2bfloat16(v);
    hi[i] = h;
    lo[i] = __float2bfloat16(v - __bfloat162float(h));
}

// ---------------- CSR build ----------------
__global__ void hist_kernel(const int* __restrict__ row, int* cnt, int e) {
    int i = blockIdx.x * blockDim.x + threadIdx.x;
    if (i < e) atomicAdd(&cnt[row[i]], 1);
}

__global__ void scan_kernel(const int* __restrict__ cnt, int* ptr, int* fill, int n) {
    __shared__ int sh[1024];
    __shared__ int carry;
    if (threadIdx.x == 0) carry = 0;
    __syncthreads();
    for (int base = 0; base < n; base += 1024) {
        int i = base + threadIdx.x;
        int v = (i < n) ? cnt[i] : 0;
        sh[threadIdx.x] = v;
        __syncthreads();
        for (int off = 1; off < 1024; off <<= 1) {
            int t = (threadIdx.x >= off) ? sh[threadIdx.x - off] : 0;
            __syncthreads();
            sh[threadIdx.x] += t;
            __syncthreads();
        }
        int excl = sh[threadIdx.x] - v;
        if (i < n) { ptr[i] = carry + excl; fill[i] = carry + excl; }
        __syncthreads();
        if (threadIdx.x == 1023) carry += sh[1023];
        __syncthreads();
    }
    if (threadIdx.x == 0) ptr[n] = carry;
}

__global__ void scatter_kernel(const int* __restrict__ row, int* fill, int* redges, int e) {
    int i = blockIdx.x * blockDim.x + threadIdx.x;
    if (i < e) {
        int pos = atomicAdd(&fill[row[i]], 1);
        redges[pos] = i;
    }
}

// ============ HMMA split-bf16 GEMM + fused attention scores ============
// CTA tile 128(m) x 64(n), BK=32, 8 warps (4m x 2n), warp tile 32x32.
// Epilogue: fp16 h store + per-row dot with a_src/a_dst -> atomicAdd into scores.
template <int NN, int KK>
__global__ __launch_bounds__(256, 2) void gemm_mma(
    const __nv_bfloat16* __restrict__ Ahi, const __nv_bfloat16* __restrict__ Alo,
    const __nv_bfloat16* __restrict__ Bhi, const __nv_bfloat16* __restrict__ Blo,
    __half* __restrict__ C,
    const float* __restrict__ Av, const float* __restrict__ Dv,  // a_src, a_dst [H*Cc]
    float* __restrict__ Ssrc, float* __restrict__ Sdst,          // [M*H]
    int H, int Cc, int M)
{
    constexpr int BK = 32;
    constexpr int NCH = KK / BK;
    constexpr int STG = 24576;   // A hi 8K | A lo 8K | B hi 4K | B lo 4K
    extern __shared__ char smem[];
    uint32_t sb = smem_u32(smem);

    int tid = threadIdx.x;
    int lane = tid & 31, wid = tid >> 5;
    int wm = wid & 3, wn = wid >> 2;
    int m0 = blockIdx.y * 128;
    int n0 = blockIdx.x * 64;

    int g = lane >> 3, lr = lane & 7;
    uint32_t aoff[2][2], boff[2][2];
#pragma unroll
    for (int mt = 0; mt < 2; mt++)
#pragma unroll
        for (int ks = 0; ks < 2; ks++) {
            int row = wm * 32 + mt * 16 + (g & 1) * 8 + lr;
            int unit = ks * 2 + (g >> 1);
            aoff[mt][ks] = SWZ64(row * 64 + unit * 16);
        }
#pragma unroll
    for (int np = 0; np < 2; np++)
#pragma unroll
        for (int ks = 0; ks < 2; ks++) {
            int row = wn * 32 + np * 16 + (g >> 1) * 8 + lr;
            int unit = ks * 2 + (g & 1);
            boff[np][ks] = 16384u + SWZ64(row * 64 + unit * 16);
        }

    int ar0 = tid >> 2, au0 = tid & 3;
    int ar1 = (tid + 256) >> 2;
    uint32_t asw0 = SWZ64(ar0 * 64 + au0 * 16);
    uint32_t asw1 = SWZ64(ar1 * 64 + au0 * 16);
    int br = tid >> 2, bu = tid & 3;
    uint32_t bsw = SWZ64(br * 64 + bu * 16);
    long bofs = (long)(n0 + br) * KK + bu * 8;

    float acc[2][4][4];
#pragma unroll
    for (int mt = 0; mt < 2; mt++)
#pragma unroll
        for (int nt = 0; nt < 4; nt++)
#pragma unroll
            for (int j = 0; j < 4; j++) acc[mt][nt][j] = 0.f;

    auto load_stage = [&](int ch, uint32_t so) {
        int k0 = ch * BK;
        {
            int grow = m0 + ar0;
            int sz = (grow < M) ? 16 : 0;
            long go = (long)((grow < M) ? grow : 0) * KK + k0 + au0 * 8;
            CPA16(sb + so + asw0, Ahi + go, sz);
            CPA16(sb + so + 8192 + asw0, Alo + go, sz);
        }
        {
            int grow = m0 + ar1;
            int sz = (grow < M) ? 16 : 0;
            long go = (long)((grow < M) ? grow : 0) * KK + k0 + au0 * 8;
            CPA16(sb + so + asw1, Ahi + go, sz);
            CPA16(sb + so + 8192 + asw1, Alo + go, sz);
        }
        {
            long go = bofs + k0;
            CPA16(sb + so + 16384 + bsw, Bhi + go, 16);
            CPA16(sb + so + 20480 + bsw, Blo + go, 16);
        }
    };

    auto compute_stage = [&](uint32_t so) {
#pragma unroll
        for (int ks = 0; ks < 2; ks++) {
            uint32_t ah[2][4], al[2][4], bh[4][2], bl[4][2];
#pragma unroll
            for (int mt = 0; mt < 2; mt++) {
                LDMX4(ah[mt][0], ah[mt][1], ah[mt][2], ah[mt][3], sb + so + aoff[mt][ks]);
                LDMX4(al[mt][0], al[mt][1], al[mt][2], al[mt][3], sb + so + 8192 + aoff[mt][ks]);
            }
#pragma unroll
            for (int np = 0; np < 2; np++) {
                LDMX4(bh[2 * np][0], bh[2 * np][1], bh[2 * np + 1][0], bh[2 * np + 1][1],
                      sb + so + boff[np][ks]);
                LDMX4(bl[2 * np][0], bl[2 * np][1], bl[2 * np + 1][0], bl[2 * np + 1][1],
                      sb + so + 4096 + boff[np][ks]);
            }
#pragma unroll
            for (int mt = 0; mt < 2; mt++)
#pragma unroll
                for (int nt = 0; nt < 4; nt++) {
                    mma16816(acc[mt][nt], ah[mt], bh[nt]);
                    mma16816(acc[mt][nt], ah[mt], bl[nt]);
                    mma16816(acc[mt][nt], al[mt], bh[nt]);
                }
        }
    };

    load_stage(0, 0);
    CPA_COMMIT();
    load_stage(1, STG);
    CPA_COMMIT();
#pragma unroll 1
    for (int ch = 0; ch < NCH; ch++) {
        uint32_t so = (uint32_t)(ch % 3) * STG;
        if (ch + 1 < NCH) { CPA_WAIT(1); } else { CPA_WAIT(0); }
        __syncthreads();
        if (ch + 2 < NCH) {
            load_stage(ch + 2, (uint32_t)((ch + 2) % 3) * STG);
            CPA_COMMIT();
        }
        compute_stage(so);
    }

    // ---- epilogue 1: fp16 h store ----
#pragma unroll
    for (int mt = 0; mt < 2; mt++) {
        int m = m0 + wm * 32 + mt * 16 + (lane >> 2);
#pragma unroll
        for (int nt = 0; nt < 4; nt++) {
            int n = n0 + wn * 32 + nt * 8 + (lane & 3) * 2;
            if (m < M)
                *reinterpret_cast<__half2*>(C + (size_t)m * NN + n) =
                    __floats2half2_rn(acc[mt][nt][0], acc[mt][nt][1]);
            if (m + 8 < M)
                *reinterpret_cast<__half2*>(C + (size_t)(m + 8) * NN + n) =
                    __floats2half2_rn(acc[mt][nt][2], acc[mt][nt][3]);
        }
    }

    // ---- epilogue 2: fused attention scores (head = n0 / Cc, CTA-uniform) ----
    {
        int head = n0 / Cc;
        float av[8], dv[8];
#pragma unroll
        for (int nt = 0; nt < 4; nt++) {
            int c0 = (n0 + wn * 32 + nt * 8 + (lane & 3) * 2) - head * Cc;
            av[2 * nt] = Av[head * Cc + c0];
            av[2 * nt + 1] = Av[head * Cc + c0 + 1];
            dv[2 * nt] = Dv[head * Cc + c0];
            dv[2 * nt + 1] = Dv[head * Cc + c0 + 1];
        }
#pragma unroll
        for (int mt = 0; mt < 2; mt++) {
            float ps0 = 0.f, pd0 = 0.f, ps1 = 0.f, pd1 = 0.f;
#pragma unroll
            for (int nt = 0; nt < 4; nt++) {
                ps0 += acc[mt][nt][0] * av[2 * nt] + acc[mt][nt][1] * av[2 * nt + 1];
                pd0 += acc[mt][nt][0] * dv[2 * nt] + acc[mt][nt][1] * dv[2 * nt + 1];
                ps1 += acc[mt][nt][2] * av[2 * nt] + acc[mt][nt][3] * av[2 * nt + 1];
                pd1 += acc[mt][nt][2] * dv[2 * nt] + acc[mt][nt][3] * dv[2 * nt + 1];
            }
#pragma unroll
            for (int o = 1; o <= 2; o <<= 1) {
                ps0 += __shfl_xor_sync(0xffffffffu, ps0, o);
                pd0 += __shfl_xor_sync(0xffffffffu, pd0, o);
                ps1 += __shfl_xor_sync(0xffffffffu, ps1, o);
                pd1 += __shfl_xor_sync(0xffffffffu, pd1, o);
            }
            if ((lane & 3) == 0) {
                int m = m0 + wm * 32 + mt * 16 + (lane >> 2);
                if (m < M) {
                    atomicAdd(&Ssrc[m * H + head], ps0);
                    atomicAdd(&Sdst[m * H + head], pd0);
                }
                if (m + 8 < M) {
                    atomicAdd(&Ssrc[(m + 8) * H + head], ps1);
                    atomicAdd(&Sdst[(m + 8) * H + head], pd1);
                }
            }
        }
    }
}

// ---------------- edge scores H=4 (vectorized) ----------------
__global__ void edge_scores4_kernel(
    const int* __restrict__ row, const int* __restrict__ col, const float* __restrict__ ew,
    const float* __restrict__ ssrc, const float* __restrict__ sdst,
    float* __restrict__ aexp, float* __restrict__ denom, int e)
{
    int i = blockIdx.x * blockDim.x + threadIdx.x;
    if (i >= e) return;
    int r = row[i], c = col[i];
    float w = ew[i];
    float4 s4 = *reinterpret_cast<const float4*>(ssrc + (size_t)r * 4);
    float4 d4 = *reinterpret_cast<const float4*>(sdst + (size_t)c * 4);
    float4 o;
    float v;
    v = s4.x + d4.x; v = (v >= 0.f) ? v : NEG_SLOPE * v; o.x = expf(v * w);
    v = s4.y + d4.y; v = (v >= 0.f) ? v : NEG_SLOPE * v; o.y = expf(v * w);
    v = s4.z + d4.z; v = (v >= 0.f) ? v : NEG_SLOPE * v; o.z = expf(v * w);
    v = s4.w + d4.w; v = (v >= 0.f) ? v : NEG_SLOPE * v; o.w = expf(v * w);
    *reinterpret_cast<float4*>(aexp + (size_t)i * 4) = o;
    atomicAdd(&denom[c * 4 + 0], o.x);
    atomicAdd(&denom[c * 4 + 1], o.y);
    atomicAdd(&denom[c * 4 + 2], o.z);
    atomicAdd(&denom[c * 4 + 3], o.w);
}

// ---------------- edge scores H=1 ----------------
__global__ void edge_scores1_kernel(
    const int* __restrict__ row, const int* __restrict__ col, const float* __restrict__ ew,
    const float* __restrict__ ssrc, const float* __restrict__ sdst,
    float* __restrict__ aexp, float* __restrict__ denom, int e)
{
    int i = blockIdx.x * blockDim.x + threadIdx.x;
    if (i >= e) return;
    int r = row[i], c = col[i];
    float v = ssrc[r] + sdst[c];
    v = (v >= 0.f) ? v : NEG_SLOPE * v;
    v = expf(v * ew[i]);
    aexp[i] = v;
    atomicAdd(&denom[c], v);
}

// ---------------- reciprocal of denominators ----------------
__global__ void rdenom_kernel(float* d, int n) {
    int i = blockIdx.x * blockDim.x + threadIdx.x;
    if (i < n) d[i] = 1.0f / (d[i] + EPS_SM);
}

// ===== fused aggregation(D=256,H=4) + bias + LN + ELU + bf16 split =====
__global__ __launch_bounds__(256) void aggln256_kernel(
    const __half* __restrict__ h, const float* __restrict__ aexp, const float* __restrict__ rden,
    const int* __restrict__ col, const int* __restrict__ rptr, const int* __restrict__ redges,
    const float* __restrict__ bias, const float* __restrict__ gam, const float* __restrict__ bet,
    __nv_bfloat16* __restrict__ hi, __nv_bfloat16* __restrict__ lo, int n)
{
    int warp = (blockIdx.x * blockDim.x + threadIdx.x) >> 5;
    int lane = threadIdx.x & 31;
    if (warp >= n) return;
    int hh = lane >> 3;
    float acc[8];
#pragma unroll
    for (int j = 0; j < 8; j++) acc[j] = 0.f;
    int s = rptr[warp], e1 = rptr[warp + 1];
    int i = s;
    for (; i + 1 < e1; i += 2) {
        int ea = redges[i], eb = redges[i + 1];
        int ca = col[ea], cb = col[eb];
        float wa = aexp[(size_t)ea * 4 + hh] * rden[(size_t)ca * 4 + hh];
        float wb = aexp[(size_t)eb * 4 + hh] * rden[(size_t)cb * 4 + hh];
        uint4 ra = *reinterpret_cast<const uint4*>(h + (size_t)ca * 256 + lane * 8);
        uint4 rb = *reinterpret_cast<const uint4*>(h + (size_t)cb * 256 + lane * 8);
        const __half2* pa = reinterpret_cast<const __half2*>(&ra);
        const __half2* pb = reinterpret_cast<const __half2*>(&rb);
#pragma unroll
        for (int j = 0; j < 4; j++) {
            float2 fa = __half22float2(pa[j]);
            float2 fb = __half22float2(pb[j]);
            acc[2 * j]     += wa * fa.x + wb * fb.x;
            acc[2 * j + 1] += wa * fa.y + wb * fb.y;
        }
    }
    if (i < e1) {
        int e = redges[i];
        int c = col[e];
        float w = aexp[(size_t)e * 4 + hh] * rden[(size_t)c * 4 + hh];
        uint4 r = *reinterpret_cast<const uint4*>(h + (size_t)c * 256 + lane * 8);
        const __half2* p = reinterpret_cast<const __half2*>(&r);
#pragma unroll
        for (int j = 0; j < 4; j++) {
            float2 f = __half22float2(p[j]);
            acc[2 * j]     += w * f.x;
            acc[2 * j + 1] += w * f.y;
        }
    }
    // bias
    const float4* bp = reinterpret_cast<const float4*>(bias + lane * 8);
    float4 b0 = bp[0], b1 = bp[1];
    acc[0] += b0.x; acc[1] += b0.y; acc[2] += b0.z; acc[3] += b0.w;
    acc[4] += b1.x; acc[5] += b1.y; acc[6] += b1.z; acc[7] += b1.w;
    // LN reduction
    float sum = 0.f, sumsq = 0.f;
#pragma unroll
    for (int j = 0; j < 8; j++) { sum += acc[j]; sumsq += acc[j] * acc[j]; }
#pragma unroll
    for (int o = 16; o; o >>= 1) {
        sum += __shfl_xor_sync(0xffffffffu, sum, o);
        sumsq += __shfl_xor_sync(0xffffffffu, sumsq, o);
    }
    float mu = sum * (1.0f / 256.0f);
    float var = sumsq * (1.0f / 256.0f) - mu * mu;
    float r = rsqrtf(var + EPS_LN);
    // LN + ELU + split
    const float4* gp = reinterpret_cast<const float4*>(gam + lane * 8);
    const float4* ep = reinterpret_cast<const float4*>(bet + lane * 8);
    float4 g0 = gp[0], g1 = gp[1], e0 = ep[0], e1v = ep[1];
    float gg[8] = {g0.x, g0.y, g0.z, g0.w, g1.x, g1.y, g1.z, g1.w};
    float ee[8] = {e0.x, e0.y, e0.z, e0.w, e1v.x, e1v.y, e1v.z, e1v.w};
    union { __nv_bfloat162 h2[4]; uint4 u; } uh, ul;
#pragma unroll
    for (int j = 0; j < 4; j++) {
        float y0 = (acc[2 * j] - mu) * r * gg[2 * j] + ee[2 * j];
        float y1 = (acc[2 * j + 1] - mu) * r * gg[2 * j + 1] + ee[2 * j + 1];
        y0 = (y0 > 0.f) ? y0 : expm1f(y0);
        y1 = (y1 > 0.f) ? y1 : expm1f(y1);
        __nv_bfloat16 h0 = __float2bfloat16(y0), h1 = __float2bfloat16(y1);
        uh.h2[j] = __nv_bfloat162(h0, h1);
        ul.h2[j] = __nv_bfloat162(__float2bfloat16(y0 - __bfloat162float(h0)),
                                  __float2bfloat16(y1 - __bfloat162float(h1)));
    }
    *reinterpret_cast<uint4*>(hi + (size_t)warp * 256 + lane * 8) = uh.u;
    *reinterpret_cast<uint4*>(lo + (size_t)warp * 256 + lane * 8) = ul.u;
}

// ===== fused aggregation(D=128,H=1) + bias + final LN -> fp32 out =====
__global__ __launch_bounds__(256) void aggln128_kernel(
    const __half* __restrict__ h, const float* __restrict__ aexp, const float* __restrict__ rden,
    const int* __restrict__ col, const int* __restrict__ rptr, const int* __restrict__ redges,
    const float* __restrict__ bias, const float* __restrict__ gam, const float* __restrict__ bet,
    float* __restrict__ out, int n)
{
    int warp = (blockIdx.x * blockDim.x + threadIdx.x) >> 5;
    int lane = threadIdx.x & 31;
    if (warp >= n) return;
    float acc[4];
#pragma unroll
    for (int j = 0; j < 4; j++) acc[j] = 0.f;
    int s = rptr[warp], e1 = rptr[warp + 1];
    int i = s;
    for (; i + 1 < e1; i += 2) {
        int ea = redges[i], eb = redges[i + 1];
        int ca = col[ea], cb = col[eb];
        float wa = aexp[ea] * rden[ca];
        float wb = aexp[eb] * rden[cb];
        uint2 ra = *reinterpret_cast<const uint2*>(h + (size_t)ca * 128 + lane * 4);
        uint2 rb = *reinterpret_cast<const uint2*>(h + (size_t)cb * 128 + lane * 4);
        const __half2* pa = reinterpret_cast<const __half2*>(&ra);
        const __half2* pb = reinterpret_cast<const __half2*>(&rb);
#pragma unroll
        for (int j = 0; j < 2; j++) {
            float2 fa = __half22float2(pa[j]);
            float2 fb = __half22float2(pb[j]);
            acc[2 * j]     += wa * fa.x + wb * fb.x;
            acc[2 * j + 1] += wa * fa.y + wb * fb.y;
        }
    }
    if (i < e1) {
        int e = redges[i];
        int c = col[e];
        float w = aexp[e] * rden[c];
        uint2 r = *reinterpret_cast<const uint2*>(h + (size_t)c * 128 + lane * 4);
        const __half2* p = reinterpret_cast<const __half2*>(&r);
#pragma unroll
        for (int j = 0; j < 2; j++) {
            float2 f = __half22float2(p[j]);
            acc[2 * j]     += w * f.x;
            acc[2 * j + 1] += w * f.y;
        }
    }
    float4 b0 = *reinterpret_cast<const float4*>(bias + lane * 4);
    acc[0] += b0.x; acc[1] += b0.y; acc[2] += b0.z; acc[3] += b0.w;
    float sum = 0.f, sumsq = 0.f;
#pragma unroll
    for (int j = 0; j < 4; j++) { sum += acc[j]; sumsq += acc[j] * acc[j]; }
#pragma unroll
    for (int o = 16; o; o >>= 1) {
        sum += __shfl_xor_sync(0xffffffffu, sum, o);
        sumsq += __shfl_xor_sync(0xffffffffu, sumsq, o);
    }
    float mu = sum * (1.0f / 128.0f);
    float var = sumsq * (1.0f / 128.0f) - mu * mu;
    float r = rsqrtf(var + EPS_LN);
    float4 g0 = *reinterpret_cast<const float4*>(gam + lane * 4);
    float4 e0 = *reinterpret_cast<const float4*>(bet + lane * 4);
    float4 o0 = make_float4((acc[0] - mu) * r * g0.x + e0.x,
                            (acc[1] - mu) * r * g0.y + e0.y,
                            (acc[2] - mu) * r * g0.z + e0.z,
                            (acc[3] - mu) * r * g0.w + e0.w);
    *reinterpret_cast<float4*>(out + (size_t)warp * 128 + lane * 4) = o0;
}

// ---------------- host orchestration ----------------
static inline int ceil_div(int a, int b) { return (a + b - 1) / b; }

extern "C" void kernel_launch(void* const* d_in, const int* in_sizes, int n_in,
                              void* d_out, int out_size) {
    const float* x   = (const float*)d_in[0];
    const int*   ei  = (const int*)d_in[1];
    const float* ew  = (const float*)d_in[2];
    const float* W1  = (const float*)d_in[3];
    const float* as1 = (const float*)d_in[4];
    const float* ad1 = (const float*)d_in[5];
    const float* b1  = (const float*)d_in[6];
    const float* g1  = (const float*)d_in[7];
    const float* be1 = (const float*)d_in[8];
    const float* W2  = (const float*)d_in[9];
    const float* as2 = (const float*)d_in[10];
    const float* ad2 = (const float*)d_in[11];
    const float* b2  = (const float*)d_in[12];
    const float* g2  = (const float*)d_in[13];
    const float* be2 = (const float*)d_in[14];
    const float* W3  = (const float*)d_in[15];
    const float* as3 = (const float*)d_in[16];
    const float* ad3 = (const float*)d_in[17];
    const float* b3  = (const float*)d_in[18];
    const float* g3  = (const float*)d_in[19];
    const float* be3 = (const float*)d_in[20];
    float* out = (float*)d_out;

    const int* row = ei;
    const int* col = ei + NEDGE;

    float *alpha, *denom, *score;
    int *cnt, *rptr, *fill, *redges;
    __half* h16;
    __nv_bfloat16 *ahi, *alo, *wthi, *wtlo;
    cudaGetSymbolAddress((void**)&h16, g_h16);
    cudaGetSymbolAddress((void**)&alpha, g_alpha);
    cudaGetSymbolAddress((void**)&denom, g_denom);
    cudaGetSymbolAddress((void**)&score, g_score);
    cudaGetSymbolAddress((void**)&cnt, g_cnt);
    cudaGetSymbolAddress((void**)&rptr, g_rptr);
    cudaGetSymbolAddress((void**)&fill, g_fill);
    cudaGetSymbolAddress((void**)&redges, g_redges);
    cudaGetSymbolAddress((void**)&ahi, g_ahi);
    cudaGetSymbolAddress((void**)&alo, g_alo);
    cudaGetSymbolAddress((void**)&wthi, g_wthi);
    cudaGetSymbolAddress((void**)&wtlo, g_wtlo);

    float* ssrc = score;
    float* sdst = score + NNODE * 4;

    const int TB = 256;
    const int eb = ceil_div(NEDGE, TB);
    const int mtiles = ceil_div(NNODE, 128);
    const int SMEM = 3 * 24576;   // 73728

    cudaFuncSetAttribute(gemm_mma<256, 384>, cudaFuncAttributeMaxDynamicSharedMemorySize, SMEM);
    cudaFuncSetAttribute(gemm_mma<256, 256>, cudaFuncAttributeMaxDynamicSharedMemorySize, SMEM);
    cudaFuncSetAttribute(gemm_mma<128, 256>, cudaFuncAttributeMaxDynamicSharedMemorySize, SMEM);

    asplit_kernel<<<ceil_div(NNODE * 384, TB), TB>>>(x, ahi, alo, NNODE * 384);         // 0
    wprep_kernel<<<ceil_div(384 * 256, TB), TB>>>(W1, wthi, wtlo, 384, 256);            // 1
    zero2_f<<<ceil_div(NNODE * 8, TB), TB>>>(score, NNODE * 8, denom, NNODE * 4);       // 2
    gemm_mma<256, 384><<<dim3(4, mtiles), 256, SMEM>>>(ahi, alo, wthi, wtlo, h16,       // 3 <- profiled
                                                       as1, ad1, ssrc, sdst, 4, 64, NNODE);
    zero_i<<<ceil_div(NNODE, TB), TB>>>(cnt, NNODE);                                    // 4
    hist_kernel<<<eb, TB>>>(row, cnt, NEDGE);                                           // 5
    scan_kernel<<<1, 1024>>>(cnt, rptr, fill, NNODE);                                   // 6
    scatter_kernel<<<eb, TB>>>(row, fill, redges, NEDGE);                               // 7

    // =============== Layer 1 (rest) ===============
    edge_scores4_kernel<<<eb, TB>>>(row, col, ew, ssrc, sdst, alpha, denom, NEDGE);
    rdenom_kernel<<<ceil_div(NNODE * 4, TB), TB>>>(denom, NNODE * 4);
    aggln256_kernel<<<ceil_div(NNODE * 32, TB), TB>>>(h16, alpha, denom, col, rptr, redges,
                                                      b1, g1, be1, ahi, alo, NNODE);

    // =============== Layer 2 ===============
    wprep_kernel<<<ceil_div(256 * 256, TB), TB>>>(W2, wthi, wtlo, 256, 256);
    zero2_f<<<ceil_div(NNODE * 8, TB), TB>>>(score, NNODE * 8, denom, NNODE * 4);
    gemm_mma<256, 256><<<dim3(4, mtiles), 256, SMEM>>>(ahi, alo, wthi, wtlo, h16,
                                                       as2, ad2, ssrc, sdst, 4, 64, NNODE);
    edge_scores4_kernel<<<eb, TB>>>(row, col, ew, ssrc, sdst, alpha, denom, NEDGE);
    rdenom_kernel<<<ceil_div(NNODE * 4, TB), TB>>>(denom, NNODE * 4);
    aggln256_kernel<<<ceil_div(NNODE * 32, TB), TB>>>(h16, alpha, denom, col, rptr, redges,
                                                      b2, g2, be2, ahi, alo, NNODE);

    // =============== Layer 3 ===============
    wprep_kernel<<<ceil_div(256 * 128, TB), TB>>>(W3, wthi, wtlo, 256, 128);
    zero2_f<<<ceil_div(NNODE * 8, TB), TB>>>(score, NNODE * 8, denom, NNODE);
    gemm_mma<128, 256><<<dim3(2, mtiles), 256, SMEM>>>(ahi, alo, wthi, wtlo, h16,
                                                       as3, ad3, ssrc, sdst, 1, 128, NNODE);
    edge_scores1_kernel<<<eb, TB>>>(row, col, ew, ssrc, sdst, alpha, denom, NEDGE);
    rdenom_kernel<<<ceil_div(NNODE, TB), TB>>>(denom, NNODE);
    aggln128_kernel<<<ceil_div(NNODE * 32, TB), TB>>>(h16, alpha, denom, col, rptr, redges,
                                                      b3, g3, be3, out, NNODE);
}

// round 8
// speedup vs baseline: 1.2631x; 1.0163x over previous
#include <cuda_runtime.h>
#include <cuda_bf16.h>
#include <cuda_fp16.h>
#include <math.h>
#include <stdint.h>

#define NNODE 50000
#define NEDGE 500000
#define DMAX  256
#define EPS_SM 1e-16f
#define EPS_LN 1e-5f
#define NEG_SLOPE 0.2f

// ---------------- scratch (device globals) ----------------
__device__ __half g_h16[NNODE * DMAX];          // GEMM output (fp16)
__device__ float g_alpha[NEDGE * 4];
__device__ float g_denom[NNODE * 4];
__device__ float g_score[NNODE * 8];            // [0..4N) = ssrc, [4N..8N) = sdst
__device__ int   g_cnt[NNODE];
__device__ int   g_rptr[NNODE + 1];
__device__ int   g_fill[NNODE];
__device__ int   g_redges[NEDGE];
__device__ __nv_bfloat16 g_ahi[NNODE * 384];
__device__ __nv_bfloat16 g_alo[NNODE * 384];
__device__ __nv_bfloat16 g_wthi[256 * 384];
__device__ __nv_bfloat16 g_wtlo[256 * 384];

// ================= PTX helpers =================
__device__ __forceinline__ uint32_t smem_u32(const void* p) {
    uint32_t a;
    asm("{ .reg .u64 t; cvta.to.shared.u64 t, %1; cvt.u32.u64 %0, t; }" : "=r"(a) : "l"(p));
    return a;
}

#define CPA16(dst, src, sz) \
    asm volatile("cp.async.cg.shared.global [%0], [%1], 16, %2;" \
                 :: "r"(dst), "l"(src), "r"(sz))
#define CPA_COMMIT() asm volatile("cp.async.commit_group;" ::: "memory")
#define CPA_WAIT(n)  asm volatile("cp.async.wait_group %0;" :: "n"(n) : "memory")

#define LDMX4(r0, r1, r2, r3, addr) \
    asm volatile("ldmatrix.sync.aligned.m8n8.x4.shared.b16 {%0,%1,%2,%3}, [%4];" \
                 : "=r"(r0), "=r"(r1), "=r"(r2), "=r"(r3) : "r"(addr))

__device__ __forceinline__ void mma16816(float* c, const uint32_t* a, const uint32_t* b) {
    asm volatile(
        "mma.sync.aligned.m16n8k16.row.col.f32.bf16.bf16.f32 "
        "{%0,%1,%2,%3}, {%4,%5,%6,%7}, {%8,%9}, {%0,%1,%2,%3};"
        : "+f"(c[0]), "+f"(c[1]), "+f"(c[2]), "+f"(c[3])
        : "r"(a[0]), "r"(a[1]), "r"(a[2]), "r"(a[3]), "r"(b[0]), "r"(b[1]));
}

#define SWZ64(b) ((b) ^ (((b) >> 3) & 0x30))

// ---------------- utility ----------------
__global__ void zero_i(int* p, int n) {
    int i = blockIdx.x * blockDim.x + threadIdx.x;
    if (i < n) p[i] = 0;
}
__global__ void zero2_f(float* p1, int n1, float* p2, int n2) {
    int i = blockIdx.x * blockDim.x + threadIdx.x;
    if (i < n1) p1[i] = 0.0f;
    if (i < n2) p2[i] = 0.0f;
}

// ---------------- weight prep: transpose + bf16 split ----------------
__global__ void wprep_kernel(const float* __restrict__ W, __nv_bfloat16* hi,
                             __nv_bfloat16* lo, int K, int Nn) {
    int i = blockIdx.x * blockDim.x + threadIdx.x;
    if (i >= K * Nn) return;
    int n = i / K, k = i - n * K;
    float v = W[(size_t)k * Nn + n];
    __nv_bfloat16 h = __float2bfloat16(v);
    hi[i] = h;
    lo[i] = __float2bfloat16(v - __bfloat162float(h));
}

// ---------------- activation split (layer-1 input x) ----------------
__global__ void asplit_kernel(const float* __restrict__ A, __nv_bfloat16* hi,
                              __nv_bfloat16* lo, int total) {
    int i = blockIdx.x * blockDim.x + threadIdx.x;
    if (i >= total) return;
    float v = A[i];
    __nv_bfloat16 h = __float2bfloat16(v);
    hi[i] = h;
    lo[i] = __float2bfloat16(v - __bfloat162float(h));
}

// ---------------- CSR build ----------------
__global__ void hist_kernel(const int* __restrict__ row, int* cnt, int e) {
    int i = blockIdx.x * blockDim.x + threadIdx.x;
    if (i < e) atomicAdd(&cnt[row[i]], 1);
}

__global__ void scan_kernel(const int* __restrict__ cnt, int* ptr, int* fill, int n) {
    __shared__ int sh[1024];
    __shared__ int carry;
    if (threadIdx.x == 0) carry = 0;
    __syncthreads();
    for (int base = 0; base < n; base += 1024) {
        int i = base + threadIdx.x;
        int v = (i < n) ? cnt[i] : 0;
        sh[threadIdx.x] = v;
        __syncthreads();
        for (int off = 1; off < 1024; off <<= 1) {
            int t = (threadIdx.x >= off) ? sh[threadIdx.x - off] : 0;
            __syncthreads();
            sh[threadIdx.x] += t;
            __syncthreads();
        }
        int excl = sh[threadIdx.x] - v;
        if (i < n) { ptr[i] = carry + excl; fill[i] = carry + excl; }
        __syncthreads();
        if (threadIdx.x == 1023) carry += sh[1023];
        __syncthreads();
    }
    if (threadIdx.x == 0) ptr[n] = carry;
}

__global__ void scatter_kernel(const int* __restrict__ row, int* fill, int* redges, int e) {
    int i = blockIdx.x * blockDim.x + threadIdx.x;
    if (i < e) {
        int pos = atomicAdd(&fill[row[i]], 1);
        redges[pos] = i;
    }
}

// ===== HMMA split-bf16 GEMM 128x128 tile + fused attention scores =====
// BK=32, 8 warps (4m x 2n), warp tile 32x64. 3-stage cp.async.
template <int NN, int KK>
__global__ __launch_bounds__(256, 2) void gemm_mma(
    const __nv_bfloat16* __restrict__ Ahi, const __nv_bfloat16* __restrict__ Alo,
    const __nv_bfloat16* __restrict__ Bhi, const __nv_bfloat16* __restrict__ Blo,
    __half* __restrict__ C,
    const float* __restrict__ Av, const float* __restrict__ Dv,
    float* __restrict__ Ssrc, float* __restrict__ Sdst,
    int H, int Cc, int M)
{
    constexpr int BK = 32;
    constexpr int NCH = KK / BK;
    constexpr int STG = 32768;   // A hi 8K | A lo 8K | B hi 8K | B lo 8K
    extern __shared__ char smem[];
    uint32_t sb = smem_u32(smem);

    int tid = threadIdx.x;
    int lane = tid & 31, wid = tid >> 5;
    int wm = wid & 3, wn = wid >> 2;
    int m0 = blockIdx.y * 128;
    int n0 = blockIdx.x * 128;

    int g = lane >> 3, lr = lane & 7;
    // A ldmatrix offsets: warp rows wm*32 + mt*16
    uint32_t aoff[2][2];
#pragma unroll
    for (int mt = 0; mt < 2; mt++)
#pragma unroll
        for (int ks = 0; ks < 2; ks++) {
            int row = wm * 32 + mt * 16 + (g & 1) * 8 + lr;
            int unit = ks * 2 + (g >> 1);
            aoff[mt][ks] = SWZ64(row * 64 + unit * 16);
        }
    // B ldmatrix offsets: warp n-rows wn*64 + np*16 (np=0..3)
    uint32_t boff[4][2];
#pragma unroll
    for (int np = 0; np < 4; np++)
#pragma unroll
        for (int ks = 0; ks < 2; ks++) {
            int row = wn * 64 + np * 16 + (g >> 1) * 8 + lr;
            int unit = ks * 2 + (g & 1);
            boff[np][ks] = 16384u + SWZ64(row * 64 + unit * 16);
        }

    // cp.async slots: A rows (tid>>2) and +64; B same pattern
    int r0 = tid >> 2, u0 = tid & 3;
    uint32_t sw0 = SWZ64(r0 * 64 + u0 * 16);
    uint32_t sw1 = SWZ64((r0 + 64) * 64 + u0 * 16);
    long bofs0 = (long)(n0 + r0) * KK + u0 * 8;
    long bofs1 = (long)(n0 + r0 + 64) * KK + u0 * 8;

    float acc[2][8][4];
#pragma unroll
    for (int mt = 0; mt < 2; mt++)
#pragma unroll
        for (int nt = 0; nt < 8; nt++)
#pragma unroll
            for (int j = 0; j < 4; j++) acc[mt][nt][j] = 0.f;

    auto load_stage = [&](int ch, uint32_t so) {
        int k0 = ch * BK;
        {
            int grow = m0 + r0;
            int sz = (grow < M) ? 16 : 0;
            long go = (long)((grow < M) ? grow : 0) * KK + k0 + u0 * 8;
            CPA16(sb + so + sw0, Ahi + go, sz);
            CPA16(sb + so + 8192 + sw0, Alo + go, sz);
        }
        {
            int grow = m0 + r0 + 64;
            int sz = (grow < M) ? 16 : 0;
            long go = (long)((grow < M) ? grow : 0) * KK + k0 + u0 * 8;
            CPA16(sb + so + sw1, Ahi + go, sz);
            CPA16(sb + so + 8192 + sw1, Alo + go, sz);
        }
        CPA16(sb + so + 16384 + sw0, Bhi + bofs0 + k0, 16);
        CPA16(sb + so + 24576 + sw0, Blo + bofs0 + k0, 16);
        CPA16(sb + so + 16384 + sw1, Bhi + bofs1 + k0, 16);
        CPA16(sb + so + 24576 + sw1, Blo + bofs1 + k0, 16);
    };

    auto compute_stage = [&](uint32_t so) {
#pragma unroll
        for (int ks = 0; ks < 2; ks++) {
            uint32_t ah[2][4], al[2][4], b[8][2];
#pragma unroll
            for (int mt = 0; mt < 2; mt++) {
                LDMX4(ah[mt][0], ah[mt][1], ah[mt][2], ah[mt][3], sb + so + aoff[mt][ks]);
                LDMX4(al[mt][0], al[mt][1], al[mt][2], al[mt][3], sb + so + 8192 + aoff[mt][ks]);
            }
            // B hi
#pragma unroll
            for (int np = 0; np < 4; np++)
                LDMX4(b[2 * np][0], b[2 * np][1], b[2 * np + 1][0], b[2 * np + 1][1],
                      sb + so + boff[np][ks]);
#pragma unroll
            for (int mt = 0; mt < 2; mt++)
#pragma unroll
                for (int nt = 0; nt < 8; nt++) {
                    mma16816(acc[mt][nt], ah[mt], b[nt]);
                    mma16816(acc[mt][nt], al[mt], b[nt]);
                }
            // B lo (reuse regs)
#pragma unroll
            for (int np = 0; np < 4; np++)
                LDMX4(b[2 * np][0], b[2 * np][1], b[2 * np + 1][0], b[2 * np + 1][1],
                      sb + so + 8192 + boff[np][ks]);
#pragma unroll
            for (int mt = 0; mt < 2; mt++)
#pragma unroll
                for (int nt = 0; nt < 8; nt++)
                    mma16816(acc[mt][nt], ah[mt], b[nt]);
        }
    };

    load_stage(0, 0);
    CPA_COMMIT();
    load_stage(1, STG);
    CPA_COMMIT();
#pragma unroll 1
    for (int ch = 0; ch < NCH; ch++) {
        uint32_t so = (uint32_t)(ch % 3) * STG;
        if (ch + 1 < NCH) { CPA_WAIT(1); } else { CPA_WAIT(0); }
        __syncthreads();
        if (ch + 2 < NCH) {
            load_stage(ch + 2, (uint32_t)((ch + 2) % 3) * STG);
            CPA_COMMIT();
        }
        compute_stage(so);
    }

    // ---- epilogue 1: fp16 h store ----
#pragma unroll
    for (int mt = 0; mt < 2; mt++) {
        int m = m0 + wm * 32 + mt * 16 + (lane >> 2);
#pragma unroll
        for (int nt = 0; nt < 8; nt++) {
            int n = n0 + wn * 64 + nt * 8 + (lane & 3) * 2;
            if (m < M)
                *reinterpret_cast<__half2*>(C + (size_t)m * NN + n) =
                    __floats2half2_rn(acc[mt][nt][0], acc[mt][nt][1]);
            if (m + 8 < M)
                *reinterpret_cast<__half2*>(C + (size_t)(m + 8) * NN + n) =
                    __floats2half2_rn(acc[mt][nt][2], acc[mt][nt][3]);
        }
    }

    // ---- epilogue 2: fused attention scores (warp-uniform head) ----
    {
        int head = (n0 + wn * 64) / Cc;
        float av[16], dv[16];
#pragma unroll
        for (int nt = 0; nt < 8; nt++) {
            int c0 = (n0 + wn * 64 + nt * 8 + (lane & 3) * 2) - head * Cc;
            av[2 * nt] = Av[head * Cc + c0];
            av[2 * nt + 1] = Av[head * Cc + c0 + 1];
            dv[2 * nt] = Dv[head * Cc + c0];
            dv[2 * nt + 1] = Dv[head * Cc + c0 + 1];
        }
#pragma unroll
        for (int mt = 0; mt < 2; mt++) {
            float ps0 = 0.f, pd0 = 0.f, ps1 = 0.f, pd1 = 0.f;
#pragma unroll
            for (int nt = 0; nt < 8; nt++) {
                ps0 += acc[mt][nt][0] * av[2 * nt] + acc[mt][nt][1] * av[2 * nt + 1];
                pd0 += acc[mt][nt][0] * dv[2 * nt] + acc[mt][nt][1] * dv[2 * nt + 1];
                ps1 += acc[mt][nt][2] * av[2 * nt] + acc[mt][nt][3] * av[2 * nt + 1];
                pd1 += acc[mt][nt][2] * dv[2 * nt] + acc[mt][nt][3] * dv[2 * nt + 1];
            }
#pragma unroll
            for (int o = 1; o <= 2; o <<= 1) {
                ps0 += __shfl_xor_sync(0xffffffffu, ps0, o);
                pd0 += __shfl_xor_sync(0xffffffffu, pd0, o);
                ps1 += __shfl_xor_sync(0xffffffffu, ps1, o);
                pd1 += __shfl_xor_sync(0xffffffffu, pd1, o);
            }
            if ((lane & 3) == 0) {
                int m = m0 + wm * 32 + mt * 16 + (lane >> 2);
                if (m < M) {
                    atomicAdd(&Ssrc[m * H + head], ps0);
                    atomicAdd(&Sdst[m * H + head], pd0);
                }
                if (m + 8 < M) {
                    atomicAdd(&Ssrc[(m + 8) * H + head], ps1);
                    atomicAdd(&Sdst[(m + 8) * H + head], pd1);
                }
            }
        }
    }
}

// ---------------- edge scores H=4 (vectorized) ----------------
__global__ void edge_scores4_kernel(
    const int* __restrict__ row, const int* __restrict__ col, const float* __restrict__ ew,
    const float* __restrict__ ssrc, const float* __restrict__ sdst,
    float* __restrict__ aexp, float* __restrict__ denom, int e)
{
    int i = blockIdx.x * blockDim.x + threadIdx.x;
    if (i >= e) return;
    int r = row[i], c = col[i];
    float w = ew[i];
    float4 s4 = *reinterpret_cast<const float4*>(ssrc + (size_t)r * 4);
    float4 d4 = *reinterpret_cast<const float4*>(sdst + (size_t)c * 4);
    float4 o;
    float v;
    v = s4.x + d4.x; v = (v >= 0.f) ? v : NEG_SLOPE * v; o.x = expf(v * w);
    v = s4.y + d4.y; v = (v >= 0.f) ? v : NEG_SLOPE * v; o.y = expf(v * w);
    v = s4.z + d4.z; v = (v >= 0.f) ? v : NEG_SLOPE * v; o.z = expf(v * w);
    v = s4.w + d4.w; v = (v >= 0.f) ? v : NEG_SLOPE * v; o.w = expf(v * w);
    *reinterpret_cast<float4*>(aexp + (size_t)i * 4) = o;
    atomicAdd(&denom[c * 4 + 0], o.x);
    atomicAdd(&denom[c * 4 + 1], o.y);
    atomicAdd(&denom[c * 4 + 2], o.z);
    atomicAdd(&denom[c * 4 + 3], o.w);
}

// ---------------- edge scores H=1 ----------------
__global__ void edge_scores1_kernel(
    const int* __restrict__ row, const int* __restrict__ col, const float* __restrict__ ew,
    const float* __restrict__ ssrc, const float* __restrict__ sdst,
    float* __restrict__ aexp, float* __restrict__ denom, int e)
{
    int i = blockIdx.x * blockDim.x + threadIdx.x;
    if (i >= e) return;
    int r = row[i], c = col[i];
    float v = ssrc[r] + sdst[c];
    v = (v >= 0.f) ? v : NEG_SLOPE * v;
    v = expf(v * ew[i]);
    aexp[i] = v;
    atomicAdd(&denom[c], v);
}

// ---------------- reciprocal of denominators ----------------
__global__ void rdenom_kernel(float* d, int n) {
    int i = blockIdx.x * blockDim.x + threadIdx.x;
    if (i < n) d[i] = 1.0f / (d[i] + EPS_SM);
}

// ===== fused aggregation(D=256,H=4) + bias + LN + ELU + bf16 split =====
__global__ __launch_bounds__(256) void aggln256_kernel(
    const __half* __restrict__ h, const float* __restrict__ aexp, const float* __restrict__ rden,
    const int* __restrict__ col, const int* __restrict__ rptr, const int* __restrict__ redges,
    const float* __restrict__ bias, const float* __restrict__ gam, const float* __restrict__ bet,
    __nv_bfloat16* __restrict__ hi, __nv_bfloat16* __restrict__ lo, int n)
{
    int warp = (blockIdx.x * blockDim.x + threadIdx.x) >> 5;
    int lane = threadIdx.x & 31;
    if (warp >= n) return;
    int hh = lane >> 3;
    float acc[8];
#pragma unroll
    for (int j = 0; j < 8; j++) acc[j] = 0.f;
    int s = rptr[warp], e1 = rptr[warp + 1];
    int i = s;
    for (; i + 1 < e1; i += 2) {
        int ea = redges[i], eb = redges[i + 1];
        int ca = col[ea], cb = col[eb];
        float wa = aexp[(size_t)ea * 4 + hh] * rden[(size_t)ca * 4 + hh];
        float wb = aexp[(size_t)eb * 4 + hh] * rden[(size_t)cb * 4 + hh];
        uint4 ra = *reinterpret_cast<const uint4*>(h + (size_t)ca * 256 + lane * 8);
        uint4 rb = *reinterpret_cast<const uint4*>(h + (size_t)cb * 256 + lane * 8);
        const __half2* pa = reinterpret_cast<const __half2*>(&ra);
        const __half2* pb = reinterpret_cast<const __half2*>(&rb);
#pragma unroll
        for (int j = 0; j < 4; j++) {
            float2 fa = __half22float2(pa[j]);
            float2 fb = __half22float2(pb[j]);
            acc[2 * j]     += wa * fa.x + wb * fb.x;
            acc[2 * j + 1] += wa * fa.y + wb * fb.y;
        }
    }
    if (i < e1) {
        int e = redges[i];
        int c = col[e];
        float w = aexp[(size_t)e * 4 + hh] * rden[(size_t)c * 4 + hh];
        uint4 r = *reinterpret_cast<const uint4*>(h + (size_t)c * 256 + lane * 8);
        const __half2* p = reinterpret_cast<const __half2*>(&r);
#pragma unroll
        for (int j = 0; j < 4; j++) {
            float2 f = __half22float2(p[j]);
            acc[2 * j]     += w * f.x;
            acc[2 * j + 1] += w * f.y;
        }
    }
    const float4* bp = reinterpret_cast<const float4*>(bias + lane * 8);
    float4 b0 = bp[0], b1 = bp[1];
    acc[0] += b0.x; acc[1] += b0.y; acc[2] += b0.z; acc[3] += b0.w;
    acc[4] += b1.x; acc[5] += b1.y; acc[6] += b1.z; acc[7] += b1.w;
    float sum = 0.f, sumsq = 0.f;
#pragma unroll
    for (int j = 0; j < 8; j++) { sum += acc[j]; sumsq += acc[j] * acc[j]; }
#pragma unroll
    for (int o = 16; o; o >>= 1) {
        sum += __shfl_xor_sync(0xffffffffu, sum, o);
        sumsq += __shfl_xor_sync(0xffffffffu, sumsq, o);
    }
    float mu = sum * (1.0f / 256.0f);
    float var = sumsq * (1.0f / 256.0f) - mu * mu;
    float r = rsqrtf(var + EPS_LN);
    const float4* gp = reinterpret_cast<const float4*>(gam + lane * 8);
    const float4* ep = reinterpret_cast<const float4*>(bet + lane * 8);
    float4 g0 = gp[0], g1 = gp[1], e0 = ep[0], e1v = ep[1];
    float gg[8] = {g0.x, g0.y, g0.z, g0.w, g1.x, g1.y, g1.z, g1.w};
    float ee[8] = {e0.x, e0.y, e0.z, e0.w, e1v.x, e1v.y, e1v.z, e1v.w};
    union { __nv_bfloat162 h2[4]; uint4 u; } uh, ul;
#pragma unroll
    for (int j = 0; j < 4; j++) {
        float y0 = (acc[2 * j] - mu) * r * gg[2 * j] + ee[2 * j];
        float y1 = (acc[2 * j + 1] - mu) * r * gg[2 * j + 1] + ee[2 * j + 1];
        y0 = (y0 > 0.f) ? y0 : expm1f(y0);
        y1 = (y1 > 0.f) ? y1 : expm1f(y1);
        __nv_bfloat16 h0 = __float2bfloat16(y0), h1 = __float2bfloat16(y1);
        uh.h2[j] = __nv_bfloat162(h0, h1);
        ul.h2[j] = __nv_bfloat162(__float2bfloat16(y0 - __bfloat162float(h0)),
                                  __float2bfloat16(y1 - __bfloat162float(h1)));
    }
    *reinterpret_cast<uint4*>(hi + (size_t)warp * 256 + lane * 8) = uh.u;
    *reinterpret_cast<uint4*>(lo + (size_t)warp * 256 + lane * 8) = ul.u;
}

// ===== fused aggregation(D=128,H=1) + bias + final LN -> fp32 out =====
__global__ __launch_bounds__(256) void aggln128_kernel(
    const __half* __restrict__ h, const float* __restrict__ aexp, const float* __restrict__ rden,
    const int* __restrict__ col, const int* __restrict__ rptr, const int* __restrict__ redges,
    const float* __restrict__ bias, const float* __restrict__ gam, const float* __restrict__ bet,
    float* __restrict__ out, int n)
{
    int warp = (blockIdx.x * blockDim.x + threadIdx.x) >> 5;
    int lane = threadIdx.x & 31;
    if (warp >= n) return;
    float acc[4];
#pragma unroll
    for (int j = 0; j < 4; j++) acc[j] = 0.f;
    int s = rptr[warp], e1 = rptr[warp + 1];
    int i = s;
    for (; i + 1 < e1; i += 2) {
        int ea = redges[i], eb = redges[i + 1];
        int ca = col[ea], cb = col[eb];
        float wa = aexp[ea] * rden[ca];
        float wb = aexp[eb] * rden[cb];
        uint2 ra = *reinterpret_cast<const uint2*>(h + (size_t)ca * 128 + lane * 4);
        uint2 rb = *reinterpret_cast<const uint2*>(h + (size_t)cb * 128 + lane * 4);
        const __half2* pa = reinterpret_cast<const __half2*>(&ra);
        const __half2* pb = reinterpret_cast<const __half2*>(&rb);
#pragma unroll
        for (int j = 0; j < 2; j++) {
            float2 fa = __half22float2(pa[j]);
            float2 fb = __half22float2(pb[j]);
            acc[2 * j]     += wa * fa.x + wb * fb.x;
            acc[2 * j + 1] += wa * fa.y + wb * fb.y;
        }
    }
    if (i < e1) {
        int e = redges[i];
        int c = col[e];
        float w = aexp[e] * rden[c];
        uint2 r = *reinterpret_cast<const uint2*>(h + (size_t)c * 128 + lane * 4);
        const __half2* p = reinterpret_cast<const __half2*>(&r);
#pragma unroll
        for (int j = 0; j < 2; j++) {
            float2 f = __half22float2(p[j]);
            acc[2 * j]     += w * f.x;
            acc[2 * j + 1] += w * f.y;
        }
    }
    float4 b0 = *reinterpret_cast<const float4*>(bias + lane * 4);
    acc[0] += b0.x; acc[1] += b0.y; acc[2] += b0.z; acc[3] += b0.w;
    float sum = 0.f, sumsq = 0.f;
#pragma unroll
    for (int j = 0; j < 4; j++) { sum += acc[j]; sumsq += acc[j] * acc[j]; }
#pragma unroll
    for (int o = 16; o; o >>= 1) {
        sum += __shfl_xor_sync(0xffffffffu, sum, o);
        sumsq += __shfl_xor_sync(0xffffffffu, sumsq, o);
    }
    float mu = sum * (1.0f / 128.0f);
    float var = sumsq * (1.0f / 128.0f) - mu * mu;
    float r = rsqrtf(var + EPS_LN);
    float4 g0 = *reinterpret_cast<const float4*>(gam + lane * 4);
    float4 e0 = *reinterpret_cast<const float4*>(bet + lane * 4);
    float4 o0 = make_float4((acc[0] - mu) * r * g0.x + e0.x,
                            (acc[1] - mu) * r * g0.y + e0.y,
                            (acc[2] - mu) * r * g0.z + e0.z,
                            (acc[3] - mu) * r * g0.w + e0.w);
    *reinterpret_cast<float4*>(out + (size_t)warp * 128 + lane * 4) = o0;
}

// ---------------- host orchestration ----------------
static inline int ceil_div(int a, int b) { return (a + b - 1) / b; }

extern "C" void kernel_launch(void* const* d_in, const int* in_sizes, int n_in,
                              void* d_out, int out_size) {
    const float* x   = (const float*)d_in[0];
    const int*   ei  = (const int*)d_in[1];
    const float* ew  = (const float*)d_in[2];
    const float* W1  = (const float*)d_in[3];
    const float* as1 = (const float*)d_in[4];
    const float* ad1 = (const float*)d_in[5];
    const float* b1  = (const float*)d_in[6];
    const float* g1  = (const float*)d_in[7];
    const float* be1 = (const float*)d_in[8];
    const float* W2  = (const float*)d_in[9];
    const float* as2 = (const float*)d_in[10];
    const float* ad2 = (const float*)d_in[11];
    const float* b2  = (const float*)d_in[12];
    const float* g2  = (const float*)d_in[13];
    const float* be2 = (const float*)d_in[14];
    const float* W3  = (const float*)d_in[15];
    const float* as3 = (const float*)d_in[16];
    const float* ad3 = (const float*)d_in[17];
    const float* b3  = (const float*)d_in[18];
    const float* g3  = (const float*)d_in[19];
    const float* be3 = (const float*)d_in[20];
    float* out = (float*)d_out;

    const int* row = ei;
    const int* col = ei + NEDGE;

    float *alpha, *denom, *score;
    int *cnt, *rptr, *fill, *redges;
    __half* h16;
    __nv_bfloat16 *ahi, *alo, *wthi, *wtlo;
    cudaGetSymbolAddress((void**)&h16, g_h16);
    cudaGetSymbolAddress((void**)&alpha, g_alpha);
    cudaGetSymbolAddress((void**)&denom, g_denom);
    cudaGetSymbolAddress((void**)&score, g_score);
    cudaGetSymbolAddress((void**)&cnt, g_cnt);
    cudaGetSymbolAddress((void**)&rptr, g_rptr);
    cudaGetSymbolAddress((void**)&fill, g_fill);
    cudaGetSymbolAddress((void**)&redges, g_redges);
    cudaGetSymbolAddress((void**)&ahi, g_ahi);
    cudaGetSymbolAddress((void**)&alo, g_alo);
    cudaGetSymbolAddress((void**)&wthi, g_wthi);
    cudaGetSymbolAddress((void**)&wtlo, g_wtlo);

    float* ssrc = score;
    float* sdst = score + NNODE * 4;

    const int TB = 256;
    const int eb = ceil_div(NEDGE, TB);
    const int mtiles = ceil_div(NNODE, 128);
    const int SMEM = 3 * 32768;   // 98304

    cudaFuncSetAttribute(gemm_mma<256, 384>, cudaFuncAttributeMaxDynamicSharedMemorySize, SMEM);
    cudaFuncSetAttribute(gemm_mma<256, 256>, cudaFuncAttributeMaxDynamicSharedMemorySize, SMEM);
    cudaFuncSetAttribute(gemm_mma<128, 256>, cudaFuncAttributeMaxDynamicSharedMemorySize, SMEM);

    asplit_kernel<<<ceil_div(NNODE * 384, TB), TB>>>(x, ahi, alo, NNODE * 384);         // 0
    wprep_kernel<<<ceil_div(384 * 256, TB), TB>>>(W1, wthi, wtlo, 384, 256);            // 1
    zero2_f<<<ceil_div(NNODE * 8, TB), TB>>>(score, NNODE * 8, denom, NNODE * 4);       // 2
    gemm_mma<256, 384><<<dim3(2, mtiles), 256, SMEM>>>(ahi, alo, wthi, wtlo, h16,       // 3 <- profiled
                                                       as1, ad1, ssrc, sdst, 4, 64, NNODE);
    zero_i<<<ceil_div(NNODE, TB), TB>>>(cnt, NNODE);                                    // 4
    hist_kernel<<<eb, TB>>>(row, cnt, NEDGE);                                           // 5
    scan_kernel<<<1, 1024>>>(cnt, rptr, fill, NNODE);                                   // 6
    scatter_kernel<<<eb, TB>>>(row, fill, redges, NEDGE);                               // 7

    // =============== Layer 1 (rest) ===============
    edge_scores4_kernel<<<eb, TB>>>(row, col, ew, ssrc, sdst, alpha, denom, NEDGE);
    rdenom_kernel<<<ceil_div(NNODE * 4, TB), TB>>>(denom, NNODE * 4);
    aggln256_kernel<<<ceil_div(NNODE * 32, TB), TB>>>(h16, alpha, denom, col, rptr, redges,
                                                      b1, g1, be1, ahi, alo, NNODE);

    // =============== Layer 2 ===============
    wprep_kernel<<<ceil_div(256 * 256, TB), TB>>>(W2, wthi, wtlo, 256, 256);
    zero2_f<<<ceil_div(NNODE * 8, TB), TB>>>(score, NNODE * 8, denom, NNODE * 4);
    gemm_mma<256, 256><<<dim3(2, mtiles), 256, SMEM>>>(ahi, alo, wthi, wtlo, h16,
                                                       as2, ad2, ssrc, sdst, 4, 64, NNODE);
    edge_scores4_kernel<<<eb, TB>>>(row, col, ew, ssrc, sdst, alpha, denom, NEDGE);
    rdenom_kernel<<<ceil_div(NNODE * 4, TB), TB>>>(denom, NNODE * 4);
    aggln256_kernel<<<ceil_div(NNODE * 32, TB), TB>>>(h16, alpha, denom, col, rptr, redges,
                                                      b2, g2, be2, ahi, alo, NNODE);

    // =============== Layer 3 ===============
    wprep_kernel<<<ceil_div(256 * 128, TB), TB>>>(W3, wthi, wtlo, 256, 128);
    zero2_f<<<ceil_div(NNODE * 8, TB), TB>>>(score, NNODE * 8, denom, NNODE);
    gemm_mma<128, 256><<<dim3(1, mtiles), 256, SMEM>>>(ahi, alo, wthi, wtlo, h16,
                                                       as3, ad3, ssrc, sdst, 1, 128, NNODE);
    edge_scores1_kernel<<<eb, TB>>>(row, col, ew, ssrc, sdst, alpha, denom, NEDGE);
    rdenom_kernel<<<ceil_div(NNODE, TB), TB>>>(denom, NNODE);
    aggln128_kernel<<<ceil_div(NNODE * 32, TB), TB>>>(h16, alpha, denom, col, rptr, redges,
                                                      b3, g3, be3, out, NNODE);
}

// round 9
// speedup vs baseline: 1.3964x; 1.1055x over previous
#include <cuda_runtime.h>
#include <cuda_fp16.h>
#include <math.h>
#include <stdint.h>

#define NNODE 50000
#define NEDGE 500000
#define DMAX  256
#define EPS_SM 1e-16f
#define EPS_LN 1e-5f
#define NEG_SLOPE 0.2f

// ---------------- scratch (device globals) ----------------
__device__ __half g_h16[NNODE * DMAX];          // GEMM output (fp16)
__device__ float g_alpha[NEDGE * 4];
__device__ float g_denom[NNODE * 4];
__device__ float g_score[NNODE * 8];            // ssrc | sdst
__device__ int   g_cnt[NNODE];
__device__ int   g_rptr[NNODE + 1];
__device__ int   g_fill[NNODE];
__device__ int   g_redges[NEDGE];
__device__ __half g_ahi[NNODE * 384];           // activation hi (fp16)
__device__ __half g_alo[NNODE * 384];           // activation lo (fp16)
__device__ __half g_wt[256 * 384];              // transposed weight fp16 [N][K]

// ================= PTX helpers =================
__device__ __forceinline__ uint32_t smem_u32(const void* p) {
    uint32_t a;
    asm("{ .reg .u64 t; cvta.to.shared.u64 t, %1; cvt.u32.u64 %0, t; }" : "=r"(a) : "l"(p));
    return a;
}

#define CPA16(dst, src, sz) \
    asm volatile("cp.async.cg.shared.global [%0], [%1], 16, %2;" \
                 :: "r"(dst), "l"(src), "r"(sz))
#define CPA_COMMIT() asm volatile("cp.async.commit_group;" ::: "memory")
#define CPA_WAIT(n)  asm volatile("cp.async.wait_group %0;" :: "n"(n) : "memory")

#define LDMX4(r0, r1, r2, r3, addr) \
    asm volatile("ldmatrix.sync.aligned.m8n8.x4.shared.b16 {%0,%1,%2,%3}, [%4];" \
                 : "=r"(r0), "=r"(r1), "=r"(r2), "=r"(r3) : "r"(addr))

__device__ __forceinline__ void mma16816h(float* c, const uint32_t* a, const uint32_t* b) {
    asm volatile(
        "mma.sync.aligned.m16n8k16.row.col.f32.f16.f16.f32 "
        "{%0,%1,%2,%3}, {%4,%5,%6,%7}, {%8,%9}, {%0,%1,%2,%3};"
        : "+f"(c[0]), "+f"(c[1]), "+f"(c[2]), "+f"(c[3])
        : "r"(a[0]), "r"(a[1]), "r"(a[2]), "r"(a[3]), "r"(b[0]), "r"(b[1]));
}

#define SWZ64(b) ((b) ^ (((b) >> 3) & 0x30))

// ---------------- utility ----------------
__global__ void zero_i(int* p, int n) {
    int i = blockIdx.x * blockDim.x + threadIdx.x;
    if (i < n) p[i] = 0;
}
__global__ void zero2_f(float* p1, int n1, float* p2, int n2) {
    int i = blockIdx.x * blockDim.x + threadIdx.x;
    if (i < n1) p1[i] = 0.0f;
    if (i < n2) p2[i] = 0.0f;
}

// ---------------- weight prep: transpose -> fp16 ----------------
__global__ void wprep_kernel(const float* __restrict__ W, __half* wt, int K, int Nn) {
    int i = blockIdx.x * blockDim.x + threadIdx.x;
    if (i >= K * Nn) return;
    int n = i / K, k = i - n * K;
    wt[i] = __float2half(W[(size_t)k * Nn + n]);
}

// ---------------- activation split (layer-1 input x), fp16 hi/lo ----------------
__global__ void asplit_kernel(const float* __restrict__ A, __half* hi, __half* lo, int total) {
    int i = blockIdx.x * blockDim.x + threadIdx.x;
    if (i >= total) return;
    float v = A[i];
    __half h = __float2half(v);
    hi[i] = h;
    lo[i] = __float2half(v - __half2float(h));
}

// ---------------- CSR build ----------------
__global__ void hist_kernel(const int* __restrict__ row, int* cnt, int e) {
    int i = blockIdx.x * blockDim.x + threadIdx.x;
    if (i < e) atomicAdd(&cnt[row[i]], 1);
}

__global__ void scan_kernel(const int* __restrict__ cnt, int* ptr, int* fill, int n) {
    __shared__ int sh[1024];
    __shared__ int carry;
    if (threadIdx.x == 0) carry = 0;
    __syncthreads();
    for (int base = 0; base < n; base += 1024) {
        int i = base + threadIdx.x;
        int v = (i < n) ? cnt[i] : 0;
        sh[threadIdx.x] = v;
        __syncthreads();
        for (int off = 1; off < 1024; off <<= 1) {
            int t = (threadIdx.x >= off) ? sh[threadIdx.x - off] : 0;
            __syncthreads();
            sh[threadIdx.x] += t;
            __syncthreads();
        }
        int excl = sh[threadIdx.x] - v;
        if (i < n) { ptr[i] = carry + excl; fill[i] = carry + excl; }
        __syncthreads();
        if (threadIdx.x == 1023) carry += sh[1023];
        __syncthreads();
    }
    if (threadIdx.x == 0) ptr[n] = carry;
}

__global__ void scatter_kernel(const int* __restrict__ row, int* fill, int* redges, int e) {
    int i = blockIdx.x * blockDim.x + threadIdx.x;
    if (i < e) {
        int pos = atomicAdd(&fill[row[i]], 1);
        redges[pos] = i;
    }
}

// ===== HMMA fp16 2-term GEMM 128x128 tile + fused attention scores =====
// A split fp16 hi/lo; B single fp16. BK=32, 8 warps (4m x 2n), warp 32x64.
template <int NN, int KK>
__global__ __launch_bounds__(256, 2) void gemm_mma(
    const __half* __restrict__ Ahi, const __half* __restrict__ Alo,
    const __half* __restrict__ Bw,
    __half* __restrict__ C,
    const float* __restrict__ Av, const float* __restrict__ Dv,
    float* __restrict__ Ssrc, float* __restrict__ Sdst,
    int H, int Cc, int M)
{
    constexpr int BK = 32;
    constexpr int NCH = KK / BK;
    constexpr int STG = 24576;   // A hi 8K | A lo 8K | B 8K
    extern __shared__ char smem[];
    uint32_t sb = smem_u32(smem);

    int tid = threadIdx.x;
    int lane = tid & 31, wid = tid >> 5;
    int wm = wid & 3, wn = wid >> 2;
    int m0 = blockIdx.y * 128;
    int n0 = blockIdx.x * 128;

    int g = lane >> 3, lr = lane & 7;
    uint32_t aoff[2][2];
#pragma unroll
    for (int mt = 0; mt < 2; mt++)
#pragma unroll
        for (int ks = 0; ks < 2; ks++) {
            int row = wm * 32 + mt * 16 + (g & 1) * 8 + lr;
            int unit = ks * 2 + (g >> 1);
            aoff[mt][ks] = SWZ64(row * 64 + unit * 16);
        }
    uint32_t boff[4][2];
#pragma unroll
    for (int np = 0; np < 4; np++)
#pragma unroll
        for (int ks = 0; ks < 2; ks++) {
            int row = wn * 64 + np * 16 + (g >> 1) * 8 + lr;
            int unit = ks * 2 + (g & 1);
            boff[np][ks] = 16384u + SWZ64(row * 64 + unit * 16);
        }

    int r0 = tid >> 2, u0 = tid & 3;
    uint32_t sw0 = SWZ64(r0 * 64 + u0 * 16);
    uint32_t sw1 = SWZ64((r0 + 64) * 64 + u0 * 16);
    long bofs0 = (long)(n0 + r0) * KK + u0 * 8;
    long bofs1 = (long)(n0 + r0 + 64) * KK + u0 * 8;

    float acc[2][8][4];
#pragma unroll
    for (int mt = 0; mt < 2; mt++)
#pragma unroll
        for (int nt = 0; nt < 8; nt++)
#pragma unroll
            for (int j = 0; j < 4; j++) acc[mt][nt][j] = 0.f;

    auto load_stage = [&](int ch, uint32_t so) {
        int k0 = ch * BK;
        {
            int grow = m0 + r0;
            int sz = (grow < M) ? 16 : 0;
            long go = (long)((grow < M) ? grow : 0) * KK + k0 + u0 * 8;
            CPA16(sb + so + sw0, Ahi + go, sz);
            CPA16(sb + so + 8192 + sw0, Alo + go, sz);
        }
        {
            int grow = m0 + r0 + 64;
            int sz = (grow < M) ? 16 : 0;
            long go = (long)((grow < M) ? grow : 0) * KK + k0 + u0 * 8;
            CPA16(sb + so + sw1, Ahi + go, sz);
            CPA16(sb + so + 8192 + sw1, Alo + go, sz);
        }
        CPA16(sb + so + 16384 + sw0, Bw + bofs0 + k0, 16);
        CPA16(sb + so + 16384 + sw1, Bw + bofs1 + k0, 16);
    };

    auto compute_stage = [&](uint32_t so) {
#pragma unroll
        for (int ks = 0; ks < 2; ks++) {
            uint32_t ah[2][4], al[2][4], b[8][2];
#pragma unroll
            for (int mt = 0; mt < 2; mt++) {
                LDMX4(ah[mt][0], ah[mt][1], ah[mt][2], ah[mt][3], sb + so + aoff[mt][ks]);
                LDMX4(al[mt][0], al[mt][1], al[mt][2], al[mt][3], sb + so + 8192 + aoff[mt][ks]);
            }
#pragma unroll
            for (int np = 0; np < 4; np++)
                LDMX4(b[2 * np][0], b[2 * np][1], b[2 * np + 1][0], b[2 * np + 1][1],
                      sb + so + boff[np][ks]);
#pragma unroll
            for (int mt = 0; mt < 2; mt++)
#pragma unroll
                for (int nt = 0; nt < 8; nt++) {
                    mma16816h(acc[mt][nt], ah[mt], b[nt]);
                    mma16816h(acc[mt][nt], al[mt], b[nt]);
                }
        }
    };

    load_stage(0, 0);
    CPA_COMMIT();
    load_stage(1, STG);
    CPA_COMMIT();
#pragma unroll 1
    for (int ch = 0; ch < NCH; ch++) {
        uint32_t so = (uint32_t)(ch % 3) * STG;
        if (ch + 1 < NCH) { CPA_WAIT(1); } else { CPA_WAIT(0); }
        __syncthreads();
        if (ch + 2 < NCH) {
            load_stage(ch + 2, (uint32_t)((ch + 2) % 3) * STG);
            CPA_COMMIT();
        }
        compute_stage(so);
    }

    // ---- epilogue 1: fp16 h store ----
#pragma unroll
    for (int mt = 0; mt < 2; mt++) {
        int m = m0 + wm * 32 + mt * 16 + (lane >> 2);
#pragma unroll
        for (int nt = 0; nt < 8; nt++) {
            int n = n0 + wn * 64 + nt * 8 + (lane & 3) * 2;
            if (m < M)
                *reinterpret_cast<__half2*>(C + (size_t)m * NN + n) =
                    __floats2half2_rn(acc[mt][nt][0], acc[mt][nt][1]);
            if (m + 8 < M)
                *reinterpret_cast<__half2*>(C + (size_t)(m + 8) * NN + n) =
                    __floats2half2_rn(acc[mt][nt][2], acc[mt][nt][3]);
        }
    }

    // ---- epilogue 2: fused attention scores (warp-uniform head) ----
    {
        int head = (n0 + wn * 64) / Cc;
        float av[16], dv[16];
#pragma unroll
        for (int nt = 0; nt < 8; nt++) {
            int c0 = (n0 + wn * 64 + nt * 8 + (lane & 3) * 2) - head * Cc;
            av[2 * nt] = Av[head * Cc + c0];
            av[2 * nt + 1] = Av[head * Cc + c0 + 1];
            dv[2 * nt] = Dv[head * Cc + c0];
            dv[2 * nt + 1] = Dv[head * Cc + c0 + 1];
        }
#pragma unroll
        for (int mt = 0; mt < 2; mt++) {
            float ps0 = 0.f, pd0 = 0.f, ps1 = 0.f, pd1 = 0.f;
#pragma unroll
            for (int nt = 0; nt < 8; nt++) {
                ps0 += acc[mt][nt][0] * av[2 * nt] + acc[mt][nt][1] * av[2 * nt + 1];
                pd0 += acc[mt][nt][0] * dv[2 * nt] + acc[mt][nt][1] * dv[2 * nt + 1];
                ps1 += acc[mt][nt][2] * av[2 * nt] + acc[mt][nt][3] * av[2 * nt + 1];
                pd1 += acc[mt][nt][2] * dv[2 * nt] + acc[mt][nt][3] * dv[2 * nt + 1];
            }
#pragma unroll
            for (int o = 1; o <= 2; o <<= 1) {
                ps0 += __shfl_xor_sync(0xffffffffu, ps0, o);
                pd0 += __shfl_xor_sync(0xffffffffu, pd0, o);
                ps1 += __shfl_xor_sync(0xffffffffu, ps1, o);
                pd1 += __shfl_xor_sync(0xffffffffu, pd1, o);
            }
            if ((lane & 3) == 0) {
                int m = m0 + wm * 32 + mt * 16 + (lane >> 2);
                if (m < M) {
                    atomicAdd(&Ssrc[m * H + head], ps0);
                    atomicAdd(&Sdst[m * H + head], pd0);
                }
                if (m + 8 < M) {
                    atomicAdd(&Ssrc[(m + 8) * H + head], ps1);
                    atomicAdd(&Sdst[(m + 8) * H + head], pd1);
                }
            }
        }
    }
}

// ---------------- edge scores H=4 (vectorized) ----------------
__global__ void edge_scores4_kernel(
    const int* __restrict__ row, const int* __restrict__ col, const float* __restrict__ ew,
    const float* __restrict__ ssrc, const float* __restrict__ sdst,
    float* __restrict__ aexp, float* __restrict__ denom, int e)
{
    int i = blockIdx.x * blockDim.x + threadIdx.x;
    if (i >= e) return;
    int r = row[i], c = col[i];
    float w = ew[i];
    float4 s4 = *reinterpret_cast<const float4*>(ssrc + (size_t)r * 4);
    float4 d4 = *reinterpret_cast<const float4*>(sdst + (size_t)c * 4);
    float4 o;
    float v;
    v = s4.x + d4.x; v = (v >= 0.f) ? v : NEG_SLOPE * v; o.x = expf(v * w);
    v = s4.y + d4.y; v = (v >= 0.f) ? v : NEG_SLOPE * v; o.y = expf(v * w);
    v = s4.z + d4.z; v = (v >= 0.f) ? v : NEG_SLOPE * v; o.z = expf(v * w);
    v = s4.w + d4.w; v = (v >= 0.f) ? v : NEG_SLOPE * v; o.w = expf(v * w);
    *reinterpret_cast<float4*>(aexp + (size_t)i * 4) = o;
    atomicAdd(&denom[c * 4 + 0], o.x);
    atomicAdd(&denom[c * 4 + 1], o.y);
    atomicAdd(&denom[c * 4 + 2], o.z);
    atomicAdd(&denom[c * 4 + 3], o.w);
}

// ---------------- edge scores H=1 ----------------
__global__ void edge_scores1_kernel(
    const int* __restrict__ row, const int* __restrict__ col, const float* __restrict__ ew,
    const float* __restrict__ ssrc, const float* __restrict__ sdst,
    float* __restrict__ aexp, float* __restrict__ denom, int e)
{
    int i = blockIdx.x * blockDim.x + threadIdx.x;
    if (i >= e) return;
    int r = row[i], c = col[i];
    float v = ssrc[r] + sdst[c];
    v = (v >= 0.f) ? v : NEG_SLOPE * v;
    v = expf(v * ew[i]);
    aexp[i] = v;
    atomicAdd(&denom[c], v);
}

// ---------------- reciprocal of denominators ----------------
__global__ void rdenom_kernel(float* d, int n) {
    int i = blockIdx.x * blockDim.x + threadIdx.x;
    if (i < n) d[i] = 1.0f / (d[i] + EPS_SM);
}

// ===== fused aggregation(D=256,H=4) + bias + LN + ELU + fp16 split =====
__global__ __launch_bounds__(256) void aggln256_kernel(
    const __half* __restrict__ h, const float* __restrict__ aexp, const float* __restrict__ rden,
    const int* __restrict__ col, const int* __restrict__ rptr, const int* __restrict__ redges,
    const float* __restrict__ bias, const float* __restrict__ gam, const float* __restrict__ bet,
    __half* __restrict__ hi, __half* __restrict__ lo, int n)
{
    int warp = (blockIdx.x * blockDim.x + threadIdx.x) >> 5;
    int lane = threadIdx.x & 31;
    if (warp >= n) return;
    int hh = lane >> 3;
    float acc[8];
#pragma unroll
    for (int j = 0; j < 8; j++) acc[j] = 0.f;
    int s = rptr[warp], e1 = rptr[warp + 1];
    int i = s;
    for (; i + 1 < e1; i += 2) {
        int ea = redges[i], eb = redges[i + 1];
        int ca = col[ea], cb = col[eb];
        float wa = aexp[(size_t)ea * 4 + hh] * rden[(size_t)ca * 4 + hh];
        float wb = aexp[(size_t)eb * 4 + hh] * rden[(size_t)cb * 4 + hh];
        uint4 ra = *reinterpret_cast<const uint4*>(h + (size_t)ca * 256 + lane * 8);
        uint4 rb = *reinterpret_cast<const uint4*>(h + (size_t)cb * 256 + lane * 8);
        const __half2* pa = reinterpret_cast<const __half2*>(&ra);
        const __half2* pb = reinterpret_cast<const __half2*>(&rb);
#pragma unroll
        for (int j = 0; j < 4; j++) {
            float2 fa = __half22float2(pa[j]);
            float2 fb = __half22float2(pb[j]);
            acc[2 * j]     += wa * fa.x + wb * fb.x;
            acc[2 * j + 1] += wa * fa.y + wb * fb.y;
        }
    }
    if (i < e1) {
        int e = redges[i];
        int c = col[e];
        float w = aexp[(size_t)e * 4 + hh] * rden[(size_t)c * 4 + hh];
        uint4 r = *reinterpret_cast<const uint4*>(h + (size_t)c * 256 + lane * 8);
        const __half2* p = reinterpret_cast<const __half2*>(&r);
#pragma unroll
        for (int j = 0; j < 4; j++) {
            float2 f = __half22float2(p[j]);
            acc[2 * j]     += w * f.x;
            acc[2 * j + 1] += w * f.y;
        }
    }
    const float4* bp = reinterpret_cast<const float4*>(bias + lane * 8);
    float4 b0 = bp[0], b1 = bp[1];
    acc[0] += b0.x; acc[1] += b0.y; acc[2] += b0.z; acc[3] += b0.w;
    acc[4] += b1.x; acc[5] += b1.y; acc[6] += b1.z; acc[7] += b1.w;
    float sum = 0.f, sumsq = 0.f;
#pragma unroll
    for (int j = 0; j < 8; j++) { sum += acc[j]; sumsq += acc[j] * acc[j]; }
#pragma unroll
    for (int o = 16; o; o >>= 1) {
        sum += __shfl_xor_sync(0xffffffffu, sum, o);
        sumsq += __shfl_xor_sync(0xffffffffu, sumsq, o);
    }
    float mu = sum * (1.0f / 256.0f);
    float var = sumsq * (1.0f / 256.0f) - mu * mu;
    float r = rsqrtf(var + EPS_LN);
    const float4* gp = reinterpret_cast<const float4*>(gam + lane * 8);
    const float4* ep = reinterpret_cast<const float4*>(bet + lane * 8);
    float4 g0 = gp[0], g1 = gp[1], e0 = ep[0], e1v = ep[1];
    float gg[8] = {g0.x, g0.y, g0.z, g0.w, g1.x, g1.y, g1.z, g1.w};
    float ee[8] = {e0.x, e0.y, e0.z, e0.w, e1v.x, e1v.y, e1v.z, e1v.w};
    union { __half2 h2[4]; uint4 u; } uh, ul;
#pragma unroll
    for (int j = 0; j < 4; j++) {
        float y0 = (acc[2 * j] - mu) * r * gg[2 * j] + ee[2 * j];
        float y1 = (acc[2 * j + 1] - mu) * r * gg[2 * j + 1] + ee[2 * j + 1];
        y0 = (y0 > 0.f) ? y0 : expm1f(y0);
        y1 = (y1 > 0.f) ? y1 : expm1f(y1);
        __half h0 = __float2half(y0), h1 = __float2half(y1);
        uh.h2[j] = __halves2half2(h0, h1);
        ul.h2[j] = __halves2half2(__float2half(y0 - __half2float(h0)),
                                  __float2half(y1 - __half2float(h1)));
    }
    *reinterpret_cast<uint4*>(hi + (size_t)warp * 256 + lane * 8) = uh.u;
    *reinterpret_cast<uint4*>(lo + (size_t)warp * 256 + lane * 8) = ul.u;
}

// ===== fused aggregation(D=128,H=1) + bias + final LN -> fp32 out =====
__global__ __launch_bounds__(256) void aggln128_kernel(
    const __half* __restrict__ h, const float* __restrict__ aexp, const float* __restrict__ rden,
    const int* __restrict__ col, const int* __restrict__ rptr, const int* __restrict__ redges,
    const float* __restrict__ bias, const float* __restrict__ gam, const float* __restrict__ bet,
    float* __restrict__ out, int n)
{
    int warp = (blockIdx.x * blockDim.x + threadIdx.x) >> 5;
    int lane = threadIdx.x & 31;
    if (warp >= n) return;
    float acc[4];
#pragma unroll
    for (int j = 0; j < 4; j++) acc[j] = 0.f;
    int s = rptr[warp], e1 = rptr[warp + 1];
    int i = s;
    for (; i + 1 < e1; i += 2) {
        int ea = redges[i], eb = redges[i + 1];
        int ca = col[ea], cb = col[eb];
        float wa = aexp[ea] * rden[ca];
        float wb = aexp[eb] * rden[cb];
        uint2 ra = *reinterpret_cast<const uint2*>(h + (size_t)ca * 128 + lane * 4);
        uint2 rb = *reinterpret_cast<const uint2*>(h + (size_t)cb * 128 + lane * 4);
        const __half2* pa = reinterpret_cast<const __half2*>(&ra);
        const __half2* pb = reinterpret_cast<const __half2*>(&rb);
#pragma unroll
        for (int j = 0; j < 2; j++) {
            float2 fa = __half22float2(pa[j]);
            float2 fb = __half22float2(pb[j]);
            acc[2 * j]     += wa * fa.x + wb * fb.x;
            acc[2 * j + 1] += wa * fa.y + wb * fb.y;
        }
    }
    if (i < e1) {
        int e = redges[i];
        int c = col[e];
        float w = aexp[e] * rden[c];
        uint2 r = *reinterpret_cast<const uint2*>(h + (size_t)c * 128 + lane * 4);
        const __half2* p = reinterpret_cast<const __half2*>(&r);
#pragma unroll
        for (int j = 0; j < 2; j++) {
            float2 f = __half22float2(p[j]);
            acc[2 * j]     += w * f.x;
            acc[2 * j + 1] += w * f.y;
        }
    }
    float4 b0 = *reinterpret_cast<const float4*>(bias + lane * 4);
    acc[0] += b0.x; acc[1] += b0.y; acc[2] += b0.z; acc[3] += b0.w;
    float sum = 0.f, sumsq = 0.f;
#pragma unroll
    for (int j = 0; j < 4; j++) { sum += acc[j]; sumsq += acc[j] * acc[j]; }
#pragma unroll
    for (int o = 16; o; o >>= 1) {
        sum += __shfl_xor_sync(0xffffffffu, sum, o);
        sumsq += __shfl_xor_sync(0xffffffffu, sumsq, o);
    }
    float mu = sum * (1.0f / 128.0f);
    float var = sumsq * (1.0f / 128.0f) - mu * mu;
    float r = rsqrtf(var + EPS_LN);
    float4 g0 = *reinterpret_cast<const float4*>(gam + lane * 4);
    float4 e0 = *reinterpret_cast<const float4*>(bet + lane * 4);
    float4 o0 = make_float4((acc[0] - mu) * r * g0.x + e0.x,
                            (acc[1] - mu) * r * g0.y + e0.y,
                            (acc[2] - mu) * r * g0.z + e0.z,
                            (acc[3] - mu) * r * g0.w + e0.w);
    *reinterpret_cast<float4*>(out + (size_t)warp * 128 + lane * 4) = o0;
}

// ---------------- host orchestration ----------------
static inline int ceil_div(int a, int b) { return (a + b - 1) / b; }

extern "C" void kernel_launch(void* const* d_in, const int* in_sizes, int n_in,
                              void* d_out, int out_size) {
    const float* x   = (const float*)d_in[0];
    const int*   ei  = (const int*)d_in[1];
    const float* ew  = (const float*)d_in[2];
    const float* W1  = (const float*)d_in[3];
    const float* as1 = (const float*)d_in[4];
    const float* ad1 = (const float*)d_in[5];
    const float* b1  = (const float*)d_in[6];
    const float* g1  = (const float*)d_in[7];
    const float* be1 = (const float*)d_in[8];
    const float* W2  = (const float*)d_in[9];
    const float* as2 = (const float*)d_in[10];
    const float* ad2 = (const float*)d_in[11];
    const float* b2  = (const float*)d_in[12];
    const float* g2  = (const float*)d_in[13];
    const float* be2 = (const float*)d_in[14];
    const float* W3  = (const float*)d_in[15];
    const float* as3 = (const float*)d_in[16];
    const float* ad3 = (const float*)d_in[17];
    const float* b3  = (const float*)d_in[18];
    const float* g3  = (const float*)d_in[19];
    const float* be3 = (const float*)d_in[20];
    float* out = (float*)d_out;

    const int* row = ei;
    const int* col = ei + NEDGE;

    float *alpha, *denom, *score;
    int *cnt, *rptr, *fill, *redges;
    __half *h16, *ahi, *alo, *wt;
    cudaGetSymbolAddress((void**)&h16, g_h16);
    cudaGetSymbolAddress((void**)&alpha, g_alpha);
    cudaGetSymbolAddress((void**)&denom, g_denom);
    cudaGetSymbolAddress((void**)&score, g_score);
    cudaGetSymbolAddress((void**)&cnt, g_cnt);
    cudaGetSymbolAddress((void**)&rptr, g_rptr);
    cudaGetSymbolAddress((void**)&fill, g_fill);
    cudaGetSymbolAddress((void**)&redges, g_redges);
    cudaGetSymbolAddress((void**)&ahi, g_ahi);
    cudaGetSymbolAddress((void**)&alo, g_alo);
    cudaGetSymbolAddress((void**)&wt, g_wt);

    float* ssrc = score;
    float* sdst = score + NNODE * 4;

    const int TB = 256;
    const int eb = ceil_div(NEDGE, TB);
    const int mtiles = ceil_div(NNODE, 128);
    const int SMEM = 3 * 24576;   // 73728

    cudaFuncSetAttribute(gemm_mma<256, 384>, cudaFuncAttributeMaxDynamicSharedMemorySize, SMEM);
    cudaFuncSetAttribute(gemm_mma<256, 256>, cudaFuncAttributeMaxDynamicSharedMemorySize, SMEM);
    cudaFuncSetAttribute(gemm_mma<128, 256>, cudaFuncAttributeMaxDynamicSharedMemorySize, SMEM);

    asplit_kernel<<<ceil_div(NNODE * 384, TB), TB>>>(x, ahi, alo, NNODE * 384);         // 0
    wprep_kernel<<<ceil_div(384 * 256, TB), TB>>>(W1, wt, 384, 256);                    // 1
    zero2_f<<<ceil_div(NNODE * 8, TB), TB>>>(score, NNODE * 8, denom, NNODE * 4);       // 2
    gemm_mma<256, 384><<<dim3(2, mtiles), 256, SMEM>>>(ahi, alo, wt, h16,               // 3 <- profiled
                                                       as1, ad1, ssrc, sdst, 4, 64, NNODE);
    zero_i<<<ceil_div(NNODE, TB), TB>>>(cnt, NNODE);                                    // 4
    hist_kernel<<<eb, TB>>>(row, cnt, NEDGE);                                           // 5
    scan_kernel<<<1, 1024>>>(cnt, rptr, fill, NNODE);                                   // 6
    scatter_kernel<<<eb, TB>>>(row, fill, redges, NEDGE);                               // 7

    // =============== Layer 1 (rest) ===============
    edge_scores4_kernel<<<eb, TB>>>(row, col, ew, ssrc, sdst, alpha, denom, NEDGE);
    rdenom_kernel<<<ceil_div(NNODE * 4, TB), TB>>>(denom, NNODE * 4);
    aggln256_kernel<<<ceil_div(NNODE * 32, TB), TB>>>(h16, alpha, denom, col, rptr, redges,
                                                      b1, g1, be1, ahi, alo, NNODE);

    // =============== Layer 2 ===============
    wprep_kernel<<<ceil_div(256 * 256, TB), TB>>>(W2, wt, 256, 256);
    zero2_f<<<ceil_div(NNODE * 8, TB), TB>>>(score, NNODE * 8, denom, NNODE * 4);
    gemm_mma<256, 256><<<dim3(2, mtiles), 256, SMEM>>>(ahi, alo, wt, h16,
                                                       as2, ad2, ssrc, sdst, 4, 64, NNODE);
    edge_scores4_kernel<<<eb, TB>>>(row, col, ew, ssrc, sdst, alpha, denom, NEDGE);
    rdenom_kernel<<<ceil_div(NNODE * 4, TB), TB>>>(denom, NNODE * 4);
    aggln256_kernel<<<ceil_div(NNODE * 32, TB), TB>>>(h16, alpha, denom, col, rptr, redges,
                                                      b2, g2, be2, ahi, alo, NNODE);

    // =============== Layer 3 ===============
    wprep_kernel<<<ceil_div(256 * 128, TB), TB>>>(W3, wt, 256, 128);
    zero2_f<<<ceil_div(NNODE * 8, TB), TB>>>(score, NNODE * 8, denom, NNODE);
    gemm_mma<128, 256><<<dim3(1, mtiles), 256, SMEM>>>(ahi, alo, wt, h16,
                                                       as3, ad3, ssrc, sdst, 1, 128, NNODE);
    edge_scores1_kernel<<<eb, TB>>>(row, col, ew, ssrc, sdst, alpha, denom, NEDGE);
    rdenom_kernel<<<ceil_div(NNODE, TB), TB>>>(denom, NNODE);
    aggln128_kernel<<<ceil_div(NNODE * 32, TB), TB>>>(h16, alpha, denom, col, rptr, redges,
                                                      b3, g3, be3, out, NNODE);
}